// round 1
// baseline (speedup 1.0000x reference)
#include <cuda_runtime.h>

#define NB 8
#define NS 2048
#define ND 512
#define NH 8
#define NL 64   // LAT == OUT == 64

// Scratch (allocation-free rule: __device__ globals)
__device__ float g_Q[NB*NH*NS*NL];     // [b][h][s][lat]
__device__ float g_K[NB*NH*NS*NL];
__device__ float g_V[NB*NH*NS*NL];
__device__ float g_O[NB*NS*NH*NL];     // [b][s][h*64+o] (head-concat layout)

// ---------------------------------------------------------------------------
// Kernel 1: fused QKV projections.
// grid = (128, 24): y -> (t = y/8 in {Q,K,V}, h = y%8); x -> 128-row tile of
// the flattened [16384, 512] activation matrix.
// ---------------------------------------------------------------------------
__global__ __launch_bounds__(256) void proj_kernel(
    const float* __restrict__ x, const float* __restrict__ WQ,
    const float* __restrict__ WK, const float* __restrict__ WV)
{
    __shared__ float As[16][128];   // As[k][m]
    __shared__ float Bs[16][64];    // Bs[k][n]

    int t = blockIdx.y >> 3;
    int h = blockIdx.y & 7;
    const float* W = (t == 0 ? WQ : (t == 1 ? WK : WV)) + (size_t)h * ND * NL;
    float* dst     = (t == 0 ? g_Q : (t == 1 ? g_K : g_V));

    int m0  = blockIdx.x * 128;
    int tid = threadIdx.x;
    int tx  = tid & 15, ty = tid >> 4;   // thread tile: rows ty*8.., cols tx*4..

    float acc[8][4];
    #pragma unroll
    for (int i = 0; i < 8; i++)
        #pragma unroll
        for (int j = 0; j < 4; j++) acc[i][j] = 0.f;

    for (int k0 = 0; k0 < ND; k0 += 16) {
        // A tile: 128 rows x 16 k, transposed into As[k][m]
        #pragma unroll
        for (int it = 0; it < 2; it++) {
            int f4 = tid + it * 256;
            int r  = f4 >> 2;
            int kc = (f4 & 3) << 2;
            float4 v = *reinterpret_cast<const float4*>(
                x + (size_t)(m0 + r) * ND + k0 + kc);
            As[kc+0][r] = v.x; As[kc+1][r] = v.y;
            As[kc+2][r] = v.z; As[kc+3][r] = v.w;
        }
        // B tile: 16 x 64 (contiguous rows of 64)
        {
            int r = tid >> 4;
            int c = (tid & 15) << 2;
            *reinterpret_cast<float4*>(&Bs[r][c]) =
                *reinterpret_cast<const float4*>(W + (size_t)(k0 + r) * NL + c);
        }
        __syncthreads();

        #pragma unroll
        for (int kk = 0; kk < 16; kk++) {
            float a[8], b[4];
            *reinterpret_cast<float4*>(&a[0]) = *reinterpret_cast<float4*>(&As[kk][ty*8]);
            *reinterpret_cast<float4*>(&a[4]) = *reinterpret_cast<float4*>(&As[kk][ty*8+4]);
            *reinterpret_cast<float4*>(&b[0]) = *reinterpret_cast<float4*>(&Bs[kk][tx*4]);
            #pragma unroll
            for (int i = 0; i < 8; i++)
                #pragma unroll
                for (int j = 0; j < 4; j++)
                    acc[i][j] += a[i] * b[j];
        }
        __syncthreads();
    }

    // write to [b][h][s][64] layout
    #pragma unroll
    for (int i = 0; i < 8; i++) {
        int m = m0 + ty * 8 + i;
        int b = m >> 11, s = m & 2047;
        float* p = dst + ((((size_t)b * NH + h) * NS + s) << 6) + (tx << 2);
        *reinterpret_cast<float4*>(p) =
            make_float4(acc[i][0], acc[i][1], acc[i][2], acc[i][3]);
    }
}

// ---------------------------------------------------------------------------
// Kernel 2: flash attention, fp32.
// One block per (b, h, q-tile of 64). 256 threads, 4x4 register tiles.
// Q and K held k-major (transposed) in smem; P staged through smem for P*V.
// ---------------------------------------------------------------------------
#define SROW 68   // padded smem row (floats), multiple of 4 for float4 alignment

__global__ __launch_bounds__(256) void attn_kernel()
{
    extern __shared__ float sm[];
    float (*Qs)[SROW] = (float(*)[SROW])(sm);              // Qs[k][r]
    float (*Ks)[SROW] = (float(*)[SROW])(sm + 64*SROW);    // Ks[k][kv]
    float (*Vs)[SROW] = (float(*)[SROW])(sm + 2*64*SROW);  // Vs[kv][c]
    float (*Ps)[SROW] = (float(*)[SROW])(sm + 3*64*SROW);  // Ps[kv][r]

    int bh = blockIdx.x >> 5;   // (b*8 + h)
    int qt = blockIdx.x & 31;
    const float* Qg = g_Q + (size_t)bh * NS * NL + (size_t)qt * 64 * NL;
    const float* Kg = g_K + (size_t)bh * NS * NL;
    const float* Vg = g_V + (size_t)bh * NS * NL;

    int tid = threadIdx.x;
    int tx = tid & 15, ty = tid >> 4;   // rows 4*ty.., cols 4*tx..

    // load Q tile transposed: Qs[k][r] = Q[r][k]
    #pragma unroll
    for (int it = 0; it < 4; it++) {
        int f4 = tid + it * 256;
        int r  = f4 >> 4;            // 16 float4 per 64-wide row
        int kc = (f4 & 15) << 2;
        float4 v = *reinterpret_cast<const float4*>(Qg + r * NL + kc);
        Qs[kc+0][r] = v.x; Qs[kc+1][r] = v.y;
        Qs[kc+2][r] = v.z; Qs[kc+3][r] = v.w;
    }

    float acc[4][4];
    #pragma unroll
    for (int i = 0; i < 4; i++)
        #pragma unroll
        for (int j = 0; j < 4; j++) acc[i][j] = 0.f;
    float mrow[4], lrow[4];
    #pragma unroll
    for (int i = 0; i < 4; i++) { mrow[i] = -1e30f; lrow[i] = 0.f; }

    for (int kt = 0; kt < NS / 64; kt++) {
        __syncthreads();   // previous iteration's reads of Ks/Vs/Ps done
        const float* Kt = Kg + (size_t)kt * 64 * NL;
        const float* Vt = Vg + (size_t)kt * 64 * NL;
        #pragma unroll
        for (int it = 0; it < 4; it++) {
            int f4 = tid + it * 256;
            int r  = f4 >> 4;
            int kc = (f4 & 15) << 2;
            float4 v = *reinterpret_cast<const float4*>(Kt + r * NL + kc);
            Ks[kc+0][r] = v.x; Ks[kc+1][r] = v.y;
            Ks[kc+2][r] = v.z; Ks[kc+3][r] = v.w;
            float4 w = *reinterpret_cast<const float4*>(Vt + r * NL + kc);
            *reinterpret_cast<float4*>(&Vs[r][kc]) = w;
        }
        __syncthreads();

        // S = Q * K^T (this block's 64x64 tile)
        float s[4][4];
        #pragma unroll
        for (int i = 0; i < 4; i++)
            #pragma unroll
            for (int j = 0; j < 4; j++) s[i][j] = 0.f;
        #pragma unroll 16
        for (int k = 0; k < 64; k++) {
            float a[4], b[4];
            *reinterpret_cast<float4*>(a) = *reinterpret_cast<float4*>(&Qs[k][ty*4]);
            *reinterpret_cast<float4*>(b) = *reinterpret_cast<float4*>(&Ks[k][tx*4]);
            #pragma unroll
            for (int i = 0; i < 4; i++)
                #pragma unroll
                for (int j = 0; j < 4; j++)
                    s[i][j] += a[i] * b[j];
        }

        // online softmax, rows owned by the 16-thread tx-group (shfl width 16)
        #pragma unroll
        for (int i = 0; i < 4; i++) {
            float mt = -1e30f;
            #pragma unroll
            for (int j = 0; j < 4; j++) {
                s[i][j] *= 0.125f;            // 1/sqrt(64)
                mt = fmaxf(mt, s[i][j]);
            }
            #pragma unroll
            for (int off = 8; off >= 1; off >>= 1)
                mt = fmaxf(mt, __shfl_xor_sync(0xffffffffu, mt, off, 16));
            float mnew  = fmaxf(mrow[i], mt);
            float alpha = __expf(mrow[i] - mnew);
            float lsum  = 0.f;
            #pragma unroll
            for (int j = 0; j < 4; j++) {
                s[i][j] = __expf(s[i][j] - mnew);
                lsum += s[i][j];
            }
            #pragma unroll
            for (int off = 8; off >= 1; off >>= 1)
                lsum += __shfl_xor_sync(0xffffffffu, lsum, off, 16);
            lrow[i] = lrow[i] * alpha + lsum;
            mrow[i] = mnew;
            #pragma unroll
            for (int j = 0; j < 4; j++) acc[i][j] *= alpha;
            // stage P transposed: Ps[kv][r]
            #pragma unroll
            for (int j = 0; j < 4; j++) Ps[tx*4+j][ty*4+i] = s[i][j];
        }
        __syncthreads();

        // acc += P * V
        #pragma unroll 8
        for (int kv = 0; kv < 64; kv++) {
            float a[4], b[4];
            *reinterpret_cast<float4*>(a) = *reinterpret_cast<float4*>(&Ps[kv][ty*4]);
            *reinterpret_cast<float4*>(b) = *reinterpret_cast<float4*>(&Vs[kv][tx*4]);
            #pragma unroll
            for (int i = 0; i < 4; i++)
                #pragma unroll
                for (int j = 0; j < 4; j++)
                    acc[i][j] += a[i] * b[j];
        }
    }

    // epilogue: normalize and write head-concat layout [b][s][h*64+o]
    int b = bh >> 3, h = bh & 7;
    #pragma unroll
    for (int i = 0; i < 4; i++) {
        float inv = 1.f / lrow[i];
        int srow = qt * 64 + ty * 4 + i;
        float* p = g_O + ((size_t)(b * NS + srow) * (NH * NL)) + h * NL + tx * 4;
        *reinterpret_cast<float4*>(p) = make_float4(
            acc[i][0]*inv, acc[i][1]*inv, acc[i][2]*inv, acc[i][3]*inv);
    }
}

// ---------------------------------------------------------------------------
// Kernel 3: output projection  O_concat[16384,512] @ WO[512,64]
// ---------------------------------------------------------------------------
__global__ __launch_bounds__(256) void out_kernel(
    const float* __restrict__ Wo, float* __restrict__ out)
{
    __shared__ float As[16][128];
    __shared__ float Bs[16][64];

    int m0  = blockIdx.x * 128;
    int tid = threadIdx.x;
    int tx  = tid & 15, ty = tid >> 4;

    float acc[8][4];
    #pragma unroll
    for (int i = 0; i < 8; i++)
        #pragma unroll
        for (int j = 0; j < 4; j++) acc[i][j] = 0.f;

    for (int k0 = 0; k0 < ND; k0 += 16) {
        #pragma unroll
        for (int it = 0; it < 2; it++) {
            int f4 = tid + it * 256;
            int r  = f4 >> 2;
            int kc = (f4 & 3) << 2;
            float4 v = *reinterpret_cast<const float4*>(
                g_O + (size_t)(m0 + r) * ND + k0 + kc);
            As[kc+0][r] = v.x; As[kc+1][r] = v.y;
            As[kc+2][r] = v.z; As[kc+3][r] = v.w;
        }
        {
            int r = tid >> 4;
            int c = (tid & 15) << 2;
            *reinterpret_cast<float4*>(&Bs[r][c]) =
                *reinterpret_cast<const float4*>(Wo + (size_t)(k0 + r) * NL + c);
        }
        __syncthreads();

        #pragma unroll
        for (int kk = 0; kk < 16; kk++) {
            float a[8], b[4];
            *reinterpret_cast<float4*>(&a[0]) = *reinterpret_cast<float4*>(&As[kk][ty*8]);
            *reinterpret_cast<float4*>(&a[4]) = *reinterpret_cast<float4*>(&As[kk][ty*8+4]);
            *reinterpret_cast<float4*>(&b[0]) = *reinterpret_cast<float4*>(&Bs[kk][tx*4]);
            #pragma unroll
            for (int i = 0; i < 8; i++)
                #pragma unroll
                for (int j = 0; j < 4; j++)
                    acc[i][j] += a[i] * b[j];
        }
        __syncthreads();
    }

    #pragma unroll
    for (int i = 0; i < 8; i++) {
        int m = m0 + ty * 8 + i;
        float* p = out + (size_t)m * NL + (tx << 2);
        *reinterpret_cast<float4*>(p) =
            make_float4(acc[i][0], acc[i][1], acc[i][2], acc[i][3]);
    }
}

// ---------------------------------------------------------------------------
extern "C" void kernel_launch(void* const* d_in, const int* in_sizes, int n_in,
                              void* d_out, int out_size)
{
    const float* x  = (const float*)d_in[0];
    const float* WQ = (const float*)d_in[1];
    const float* WK = (const float*)d_in[2];
    const float* WV = (const float*)d_in[3];
    const float* WO = (const float*)d_in[4];
    float* out = (float*)d_out;

    proj_kernel<<<dim3(128, 24), 256>>>(x, WQ, WK, WV);

    size_t smem = 4 * 64 * SROW * sizeof(float);   // 69,632 B
    cudaFuncSetAttribute(attn_kernel,
                         cudaFuncAttributeMaxDynamicSharedMemorySize, (int)smem);
    attn_kernel<<<NB * NH * (NS / 64), 256, smem>>>();

    out_kernel<<<128, 256>>>(WO, out);
}

// round 3
// speedup vs baseline: 2.1394x; 2.1394x over previous
#include <cuda_runtime.h>
#include <cstdint>

#define NB 8
#define NS 2048
#define ND 512
#define NH 8
#define NL 64   // LAT == OUT == 64

// Scratch (allocation-free rule: __device__ globals)
__device__ float g_Q[NB*NH*NS*NL];     // [b][h][s][lat]
__device__ float g_K[NB*NH*NS*NL];
__device__ float g_V[NB*NH*NS*NL];
__device__ float g_O[NB*NS*NH*NL];     // [b][s][h*64+o] (head-concat layout)

// ===========================================================================
// helpers
// ===========================================================================
__device__ __forceinline__ uint32_t f2tf(float f) {
    uint32_t u;
    asm("cvt.rna.tf32.f32 %0, %1;" : "=r"(u) : "f"(f));
    return u;
}
__device__ __forceinline__ float fexp2(float x) {
    float r;
    asm("ex2.approx.ftz.f32 %0, %1;" : "=f"(r) : "f"(x));
    return r;
}
// D += A*B, m16n8k8 tf32
__device__ __forceinline__ void mma_tf32(
    float& d0, float& d1, float& d2, float& d3,
    uint32_t a0, uint32_t a1, uint32_t a2, uint32_t a3,
    uint32_t b0, uint32_t b1)
{
    asm volatile(
        "mma.sync.aligned.m16n8k8.row.col.f32.tf32.tf32.f32 "
        "{%0,%1,%2,%3}, {%4,%5,%6,%7}, {%8,%9}, {%0,%1,%2,%3};\n"
        : "+f"(d0), "+f"(d1), "+f"(d2), "+f"(d3)
        : "r"(a0), "r"(a1), "r"(a2), "r"(a3), "r"(b0), "r"(b1));
}

// ---------------------------------------------------------------------------
// Kernel 1: fused QKV projections (FFMA)
// ---------------------------------------------------------------------------
__global__ __launch_bounds__(256) void proj_kernel(
    const float* __restrict__ x, const float* __restrict__ WQ,
    const float* __restrict__ WK, const float* __restrict__ WV)
{
    __shared__ float As[16][128];
    __shared__ float Bs[16][64];

    int t = blockIdx.y >> 3;
    int h = blockIdx.y & 7;
    const float* W = (t == 0 ? WQ : (t == 1 ? WK : WV)) + (size_t)h * ND * NL;
    float* dst     = (t == 0 ? g_Q : (t == 1 ? g_K : g_V));

    int m0  = blockIdx.x * 128;
    int tid = threadIdx.x;
    int tx  = tid & 15, ty = tid >> 4;

    float acc[8][4];
    #pragma unroll
    for (int i = 0; i < 8; i++)
        #pragma unroll
        for (int j = 0; j < 4; j++) acc[i][j] = 0.f;

    for (int k0 = 0; k0 < ND; k0 += 16) {
        #pragma unroll
        for (int it = 0; it < 2; it++) {
            int f4 = tid + it * 256;
            int r  = f4 >> 2;
            int kc = (f4 & 3) << 2;
            float4 v = *reinterpret_cast<const float4*>(
                x + (size_t)(m0 + r) * ND + k0 + kc);
            As[kc+0][r] = v.x; As[kc+1][r] = v.y;
            As[kc+2][r] = v.z; As[kc+3][r] = v.w;
        }
        {
            int r = tid >> 4;
            int c = (tid & 15) << 2;
            *reinterpret_cast<float4*>(&Bs[r][c]) =
                *reinterpret_cast<const float4*>(W + (size_t)(k0 + r) * NL + c);
        }
        __syncthreads();

        #pragma unroll
        for (int kk = 0; kk < 16; kk++) {
            float a[8], b[4];
            *reinterpret_cast<float4*>(&a[0]) = *reinterpret_cast<float4*>(&As[kk][ty*8]);
            *reinterpret_cast<float4*>(&a[4]) = *reinterpret_cast<float4*>(&As[kk][ty*8+4]);
            *reinterpret_cast<float4*>(&b[0]) = *reinterpret_cast<float4*>(&Bs[kk][tx*4]);
            #pragma unroll
            for (int i = 0; i < 8; i++)
                #pragma unroll
                for (int j = 0; j < 4; j++)
                    acc[i][j] += a[i] * b[j];
        }
        __syncthreads();
    }

    #pragma unroll
    for (int i = 0; i < 8; i++) {
        int m = m0 + ty * 8 + i;
        int b = m >> 11, s = m & 2047;
        float* p = dst + ((((size_t)b * NH + h) * NS + s) << 6) + (tx << 2);
        *reinterpret_cast<float4*>(p) =
            make_float4(acc[i][0], acc[i][1], acc[i][2], acc[i][3]);
    }
}

// ---------------------------------------------------------------------------
// Kernel 2: flash attention on mma.sync tf32 (m16n8k8).
// CTA = (b, h, 128 q rows). 8 warps; warp w owns q rows [16w, 16w+16).
// kv tiles of 64, 32 iterations.
// SMEM (dynamic, u32 tf32 bits):
//   Ks[64][68]   K tile (row kv, col lat)
//   Vs[64][72]   V tile (row kv, col out)
//   Ps[8][16][68] per-warp P staging
// ---------------------------------------------------------------------------
#define KSTR 68
#define VSTR 72
#define PSTR 68
#define ATTN_SMEM ((64*KSTR + 64*VSTR + 8*16*PSTR) * 4)

__global__ __launch_bounds__(256) void attn_mma()
{
    extern __shared__ uint32_t dsm[];
    uint32_t* Ks = dsm;                 // 64*KSTR
    uint32_t* Vs = Ks + 64 * KSTR;      // 64*VSTR
    uint32_t* Ps = Vs + 64 * VSTR;      // 8*16*PSTR

    int tid  = threadIdx.x;
    int w    = tid >> 5;
    int lane = tid & 31;
    int g    = lane >> 2;     // row group 0..7
    int t    = lane & 3;      // thread-in-quad 0..3
    uint32_t* Pw = Ps + w * 16 * PSTR;

    int bh = blockIdx.x >> 4;
    int qt = blockIdx.x & 15;
    const float* Qg = g_Q + (size_t)bh * NS * NL + (size_t)(qt * 128 + w * 16) * NL;
    const float* Kg = g_K + (size_t)bh * NS * NL;
    const float* Vg = g_V + (size_t)bh * NS * NL;

    const float sc = 0.125f * 1.44269504088896340736f;  // (1/sqrt(64))*log2(e)

    // ---- Q fragments, pre-scaled, tf32, held in registers ----
    uint32_t qa[8][4];
    #pragma unroll
    for (int c = 0; c < 8; c++) {
        qa[c][0] = f2tf(Qg[(size_t)g       * NL + 8*c + t    ] * sc);
        qa[c][1] = f2tf(Qg[(size_t)(g + 8) * NL + 8*c + t    ] * sc);
        qa[c][2] = f2tf(Qg[(size_t)g       * NL + 8*c + t + 4] * sc);
        qa[c][3] = f2tf(Qg[(size_t)(g + 8) * NL + 8*c + t + 4] * sc);
    }

    float o[8][4];
    #pragma unroll
    for (int j = 0; j < 8; j++)
        #pragma unroll
        for (int i = 0; i < 4; i++) o[j][i] = 0.f;
    float m0 = -1e30f, m1 = -1e30f, l0 = 0.f, l1 = 0.f;

    for (int it = 0; it < NS / 64; it++) {
        __syncthreads();   // prior iter done reading Ks/Vs
        // ---- load K,V tiles (64x64 f32 each) as tf32 ----
        const float* Kt = Kg + (size_t)it * 64 * NL;
        const float* Vt = Vg + (size_t)it * 64 * NL;
        #pragma unroll
        for (int i = 0; i < 4; i++) {
            int f4 = tid + i * 256;           // 0..1023
            int r  = f4 >> 4;
            int c4 = (f4 & 15) << 2;
            float4 kv = *reinterpret_cast<const float4*>(Kt + (size_t)r * NL + c4);
            uint32_t* d = Ks + r * KSTR + c4;
            d[0] = f2tf(kv.x); d[1] = f2tf(kv.y); d[2] = f2tf(kv.z); d[3] = f2tf(kv.w);
            float4 vv = *reinterpret_cast<const float4*>(Vt + (size_t)r * NL + c4);
            uint32_t* e = Vs + r * VSTR + c4;
            e[0] = f2tf(vv.x); e[1] = f2tf(vv.y); e[2] = f2tf(vv.z); e[3] = f2tf(vv.w);
        }
        __syncthreads();

        // ---- S = Q K^T : 8 n-tiles (kv), 8 k-chunks (lat) ----
        float s[8][4];
        #pragma unroll
        for (int j = 0; j < 8; j++) {
            s[j][0] = s[j][1] = s[j][2] = s[j][3] = 0.f;
            #pragma unroll
            for (int c = 0; c < 8; c++) {
                uint32_t b0 = Ks[(8*j + g) * KSTR + 8*c + t];
                uint32_t b1 = Ks[(8*j + g) * KSTR + 8*c + t + 4];
                mma_tf32(s[j][0], s[j][1], s[j][2], s[j][3],
                         qa[c][0], qa[c][1], qa[c][2], qa[c][3], b0, b1);
            }
        }

        // ---- online softmax (rows g and g+8; quad = lanes sharing a row) ----
        float mt0 = s[0][0], mt1 = s[0][2];
        #pragma unroll
        for (int j = 0; j < 8; j++) {
            mt0 = fmaxf(mt0, fmaxf(s[j][0], s[j][1]));
            mt1 = fmaxf(mt1, fmaxf(s[j][2], s[j][3]));
        }
        #pragma unroll
        for (int off = 1; off <= 2; off <<= 1) {
            mt0 = fmaxf(mt0, __shfl_xor_sync(0xffffffffu, mt0, off, 4));
            mt1 = fmaxf(mt1, __shfl_xor_sync(0xffffffffu, mt1, off, 4));
        }
        float mn0 = fmaxf(m0, mt0), mn1 = fmaxf(m1, mt1);
        float a0 = fexp2(m0 - mn0), a1 = fexp2(m1 - mn1);
        float ls0 = 0.f, ls1 = 0.f;
        #pragma unroll
        for (int j = 0; j < 8; j++) {
            s[j][0] = fexp2(s[j][0] - mn0); ls0 += s[j][0];
            s[j][1] = fexp2(s[j][1] - mn0); ls0 += s[j][1];
            s[j][2] = fexp2(s[j][2] - mn1); ls1 += s[j][2];
            s[j][3] = fexp2(s[j][3] - mn1); ls1 += s[j][3];
        }
        #pragma unroll
        for (int off = 1; off <= 2; off <<= 1) {
            ls0 += __shfl_xor_sync(0xffffffffu, ls0, off, 4);
            ls1 += __shfl_xor_sync(0xffffffffu, ls1, off, 4);
        }
        l0 = l0 * a0 + ls0; m0 = mn0;
        l1 = l1 * a1 + ls1; m1 = mn1;
        #pragma unroll
        for (int j = 0; j < 8; j++) {
            o[j][0] *= a0; o[j][1] *= a0; o[j][2] *= a1; o[j][3] *= a1;
        }

        // ---- stage P (tf32) in per-warp smem: C-layout -> row-major ----
        #pragma unroll
        for (int j = 0; j < 8; j++) {
            uint32_t* p0 = Pw + g       * PSTR + 8*j + 2*t;
            uint32_t* p1 = Pw + (g + 8) * PSTR + 8*j + 2*t;
            p0[0] = f2tf(s[j][0]); p0[1] = f2tf(s[j][1]);
            p1[0] = f2tf(s[j][2]); p1[1] = f2tf(s[j][3]);
        }
        __syncwarp();

        // ---- A-fragments of P (k = kv, 8 chunks) ----
        uint32_t pa[8][4];
        #pragma unroll
        for (int c = 0; c < 8; c++) {
            pa[c][0] = Pw[g       * PSTR + 8*c + t    ];
            pa[c][1] = Pw[(g + 8) * PSTR + 8*c + t    ];
            pa[c][2] = Pw[g       * PSTR + 8*c + t + 4];
            pa[c][3] = Pw[(g + 8) * PSTR + 8*c + t + 4];
        }

        // ---- O += P V : 8 n-tiles (out), 8 k-chunks (kv) ----
        #pragma unroll
        for (int j = 0; j < 8; j++) {
            #pragma unroll
            for (int c = 0; c < 8; c++) {
                uint32_t b0 = Vs[(8*c + t)     * VSTR + 8*j + g];
                uint32_t b1 = Vs[(8*c + t + 4) * VSTR + 8*j + g];
                mma_tf32(o[j][0], o[j][1], o[j][2], o[j][3],
                         pa[c][0], pa[c][1], pa[c][2], pa[c][3], b0, b1);
            }
        }
    }

    // ---- normalize + write head-concat layout [b][s][h*64+o] ----
    {
        int b = bh >> 3, h = bh & 7;
        float inv0 = 1.f / l0, inv1 = 1.f / l1;
        int r0 = qt * 128 + w * 16 + g;
        float* p0 = g_O + ((size_t)(b * NS + r0)     * (NH * NL)) + h * NL;
        float* p1 = g_O + ((size_t)(b * NS + r0 + 8) * (NH * NL)) + h * NL;
        #pragma unroll
        for (int j = 0; j < 8; j++) {
            *reinterpret_cast<float2*>(p0 + 8*j + 2*t) =
                make_float2(o[j][0] * inv0, o[j][1] * inv0);
            *reinterpret_cast<float2*>(p1 + 8*j + 2*t) =
                make_float2(o[j][2] * inv1, o[j][3] * inv1);
        }
    }
}

// ---------------------------------------------------------------------------
// Kernel 3: output projection (FFMA)
// ---------------------------------------------------------------------------
__global__ __launch_bounds__(256) void out_kernel(
    const float* __restrict__ Wo, float* __restrict__ out)
{
    __shared__ float As[16][128];
    __shared__ float Bs[16][64];

    int m0  = blockIdx.x * 128;
    int tid = threadIdx.x;
    int tx  = tid & 15, ty = tid >> 4;

    float acc[8][4];
    #pragma unroll
    for (int i = 0; i < 8; i++)
        #pragma unroll
        for (int j = 0; j < 4; j++) acc[i][j] = 0.f;

    for (int k0 = 0; k0 < ND; k0 += 16) {
        #pragma unroll
        for (int it = 0; it < 2; it++) {
            int f4 = tid + it * 256;
            int r  = f4 >> 2;
            int kc = (f4 & 3) << 2;
            float4 v = *reinterpret_cast<const float4*>(
                g_O + (size_t)(m0 + r) * ND + k0 + kc);
            As[kc+0][r] = v.x; As[kc+1][r] = v.y;
            As[kc+2][r] = v.z; As[kc+3][r] = v.w;
        }
        {
            int r = tid >> 4;
            int c = (tid & 15) << 2;
            *reinterpret_cast<float4*>(&Bs[r][c]) =
                *reinterpret_cast<const float4*>(Wo + (size_t)(k0 + r) * NL + c);
        }
        __syncthreads();

        #pragma unroll
        for (int kk = 0; kk < 16; kk++) {
            float a[8], b[4];
            *reinterpret_cast<float4*>(&a[0]) = *reinterpret_cast<float4*>(&As[kk][ty*8]);
            *reinterpret_cast<float4*>(&a[4]) = *reinterpret_cast<float4*>(&As[kk][ty*8+4]);
            *reinterpret_cast<float4*>(&b[0]) = *reinterpret_cast<float4*>(&Bs[kk][tx*4]);
            #pragma unroll
            for (int i = 0; i < 8; i++)
                #pragma unroll
                for (int j = 0; j < 4; j++)
                    acc[i][j] += a[i] * b[j];
        }
        __syncthreads();
    }

    #pragma unroll
    for (int i = 0; i < 8; i++) {
        int m = m0 + ty * 8 + i;
        float* p = out + (size_t)m * NL + (tx << 2);
        *reinterpret_cast<float4*>(p) =
            make_float4(acc[i][0], acc[i][1], acc[i][2], acc[i][3]);
    }
}

// ---------------------------------------------------------------------------
extern "C" void kernel_launch(void* const* d_in, const int* in_sizes, int n_in,
                              void* d_out, int out_size)
{
    const float* x  = (const float*)d_in[0];
    const float* WQ = (const float*)d_in[1];
    const float* WK = (const float*)d_in[2];
    const float* WV = (const float*)d_in[3];
    const float* WO = (const float*)d_in[4];
    float* out = (float*)d_out;

    proj_kernel<<<dim3(128, 24), 256>>>(x, WQ, WK, WV);

    cudaFuncSetAttribute(attn_mma, cudaFuncAttributeMaxDynamicSharedMemorySize,
                         ATTN_SMEM);
    attn_mma<<<NB * NH * (NS / 128), 256, ATTN_SMEM>>>();

    out_kernel<<<128, 256>>>(WO, out);
}

// round 6
// speedup vs baseline: 3.0207x; 1.4120x over previous
#include <cuda_runtime.h>
#include <cstdint>

#define NB 8
#define NS 2048
#define ND 512
#define NH 8
#define NL 64   // LAT == OUT == 64

// Scratch (allocation-free rule: __device__ globals)
__device__ float g_Q[NB*NH*NS*NL];     // [b][h][s][lat]
__device__ float g_K[NB*NH*NS*NL];
__device__ float g_V[NB*NH*NS*NL];
__device__ float g_O[NB*NS*NH*NL];     // [b][s][h*64+o] (head-concat layout)

// ===========================================================================
// helpers
// ===========================================================================
__device__ __forceinline__ uint32_t f2tf(float f) {
    uint32_t u;
    asm("cvt.rna.tf32.f32 %0, %1;" : "=r"(u) : "f"(f));
    return u;
}
__device__ __forceinline__ float fexp2(float x) {
    float r;
    asm("ex2.approx.ftz.f32 %0, %1;" : "=f"(r) : "f"(x));
    return r;
}
// D += A*B, m16n8k8 tf32
__device__ __forceinline__ void mma_tf32(
    float& d0, float& d1, float& d2, float& d3,
    uint32_t a0, uint32_t a1, uint32_t a2, uint32_t a3,
    uint32_t b0, uint32_t b1)
{
    asm volatile(
        "mma.sync.aligned.m16n8k8.row.col.f32.tf32.tf32.f32 "
        "{%0,%1,%2,%3}, {%4,%5,%6,%7}, {%8,%9}, {%0,%1,%2,%3};\n"
        : "+f"(d0), "+f"(d1), "+f"(d2), "+f"(d3)
        : "r"(a0), "r"(a1), "r"(a2), "r"(a3), "r"(b0), "r"(b1));
}

// ---------------------------------------------------------------------------
// Kernel 1: fused QKV projections on mma.sync tf32.
// Grid (128 row-tiles, 8 heads). CTA computes Q,K,V [128 rows x 64] for one
// head, staging one X tile per k-step (3x reuse).
// 8 warps, warp w owns rows [16w,16w+16). Accumulators o[3][8][4].
//   Xs[128][68] tf32   A-frag reads: bank = 4g+t  (conflict-free)
//   Ws[3][64][72] tf32 B-frag reads: bank = 8t+g  (conflict-free)
// ---------------------------------------------------------------------------
#define XSTR 68
#define WSTR 72
#define PROJ_SMEM ((128*XSTR + 3*64*WSTR) * 4)

__global__ __launch_bounds__(256) void proj_mma(
    const float* __restrict__ x, const float* __restrict__ WQ,
    const float* __restrict__ WK, const float* __restrict__ WV)
{
    extern __shared__ uint32_t psm[];
    uint32_t* Xs = psm;                  // 128*XSTR
    uint32_t* Ws = psm + 128 * XSTR;     // 3 * 64*WSTR

    int tid  = threadIdx.x;
    int w    = tid >> 5;
    int lane = tid & 31;
    int g    = lane >> 2;
    int t    = lane & 3;

    int h  = blockIdx.y;
    int m0 = blockIdx.x * 128;
    const float* W0 = WQ + (size_t)h * ND * NL;
    const float* W1 = WK + (size_t)h * ND * NL;
    const float* W2 = WV + (size_t)h * ND * NL;

    float o[3][8][4];
    #pragma unroll
    for (int u = 0; u < 3; u++)
        #pragma unroll
        for (int j = 0; j < 8; j++)
            #pragma unroll
            for (int i = 0; i < 4; i++) o[u][j][i] = 0.f;

    for (int k0 = 0; k0 < ND; k0 += 64) {
        __syncthreads();
        // X tile [128,64] -> tf32 smem  (128*16 = 2048 float4 -> 8 iters x 256 thr)
        #pragma unroll
        for (int i = 0; i < 8; i++) {
            int f4 = tid + i * 256;
            int r  = f4 >> 4;            // 0..127
            int c4 = (f4 & 15) << 2;
            float4 v = *reinterpret_cast<const float4*>(
                x + (size_t)(m0 + r) * ND + k0 + c4);
            uint32_t* d = Xs + r * XSTR + c4;
            d[0]=f2tf(v.x); d[1]=f2tf(v.y); d[2]=f2tf(v.z); d[3]=f2tf(v.w);
        }
        // W tiles [64,64] x3 -> tf32 smem (64*16 = 1024 float4 -> 4 iters)
        #pragma unroll
        for (int u = 0; u < 3; u++) {
            const float* Wg = (u == 0 ? W0 : u == 1 ? W1 : W2);
            #pragma unroll
            for (int i = 0; i < 4; i++) {
                int f4 = tid + i * 256;
                int r  = f4 >> 4;
                int c4 = (f4 & 15) << 2;
                float4 v = *reinterpret_cast<const float4*>(
                    Wg + (size_t)(k0 + r) * NL + c4);
                uint32_t* d = Ws + u * 64 * WSTR + r * WSTR + c4;
                d[0]=f2tf(v.x); d[1]=f2tf(v.y); d[2]=f2tf(v.z); d[3]=f2tf(v.w);
            }
        }
        __syncthreads();

        #pragma unroll
        for (int c = 0; c < 8; c++) {
            uint32_t a0 = Xs[(16*w + g)     * XSTR + 8*c + t    ];
            uint32_t a1 = Xs[(16*w + g + 8) * XSTR + 8*c + t    ];
            uint32_t a2 = Xs[(16*w + g)     * XSTR + 8*c + t + 4];
            uint32_t a3 = Xs[(16*w + g + 8) * XSTR + 8*c + t + 4];
            #pragma unroll
            for (int u = 0; u < 3; u++) {
                const uint32_t* Wu = Ws + u * 64 * WSTR;
                #pragma unroll
                for (int j = 0; j < 8; j++) {
                    uint32_t b0 = Wu[(8*c + t)     * WSTR + 8*j + g];
                    uint32_t b1 = Wu[(8*c + t + 4) * WSTR + 8*j + g];
                    mma_tf32(o[u][j][0], o[u][j][1], o[u][j][2], o[u][j][3],
                             a0, a1, a2, a3, b0, b1);
                }
            }
        }
    }

    // write to [b][h][s][64]
    int m = m0 + 16 * w + g;
    int b = m >> 11, s = m & 2047;
    size_t base0 = (((size_t)b * NH + h) * NS + s)     << 6;
    size_t base1 = (((size_t)b * NH + h) * NS + s + 8) << 6;
    #pragma unroll
    for (int u = 0; u < 3; u++) {
        float* dst = (u == 0 ? g_Q : u == 1 ? g_K : g_V);
        #pragma unroll
        for (int j = 0; j < 8; j++) {
            *reinterpret_cast<float2*>(dst + base0 + 8*j + 2*t) =
                make_float2(o[u][j][0], o[u][j][1]);
            *reinterpret_cast<float2*>(dst + base1 + 8*j + 2*t) =
                make_float2(o[u][j][2], o[u][j][3]);
        }
    }
}

// ---------------------------------------------------------------------------
// Kernel 2: flash attention on mma.sync tf32 (m16n8k8). (unchanged from R3)
// ---------------------------------------------------------------------------
#define KSTR 68
#define VSTR 72
#define PSTR 68
#define ATTN_SMEM ((64*KSTR + 64*VSTR + 8*16*PSTR) * 4)

__global__ __launch_bounds__(256) void attn_mma()
{
    extern __shared__ uint32_t dsm[];
    uint32_t* Ks = dsm;                 // 64*KSTR
    uint32_t* Vs = Ks + 64 * KSTR;      // 64*VSTR
    uint32_t* Ps = Vs + 64 * VSTR;      // 8*16*PSTR

    int tid  = threadIdx.x;
    int w    = tid >> 5;
    int lane = tid & 31;
    int g    = lane >> 2;
    int t    = lane & 3;
    uint32_t* Pw = Ps + w * 16 * PSTR;

    int bh = blockIdx.x >> 4;
    int qt = blockIdx.x & 15;
    const float* Qg = g_Q + (size_t)bh * NS * NL + (size_t)(qt * 128 + w * 16) * NL;
    const float* Kg = g_K + (size_t)bh * NS * NL;
    const float* Vg = g_V + (size_t)bh * NS * NL;

    const float sc = 0.125f * 1.44269504088896340736f;

    uint32_t qa[8][4];
    #pragma unroll
    for (int c = 0; c < 8; c++) {
        qa[c][0] = f2tf(Qg[(size_t)g       * NL + 8*c + t    ] * sc);
        qa[c][1] = f2tf(Qg[(size_t)(g + 8) * NL + 8*c + t    ] * sc);
        qa[c][2] = f2tf(Qg[(size_t)g       * NL + 8*c + t + 4] * sc);
        qa[c][3] = f2tf(Qg[(size_t)(g + 8) * NL + 8*c + t + 4] * sc);
    }

    float o[8][4];
    #pragma unroll
    for (int j = 0; j < 8; j++)
        #pragma unroll
        for (int i = 0; i < 4; i++) o[j][i] = 0.f;
    float m0 = -1e30f, m1 = -1e30f, l0 = 0.f, l1 = 0.f;

    for (int it = 0; it < NS / 64; it++) {
        __syncthreads();
        const float* Kt = Kg + (size_t)it * 64 * NL;
        const float* Vt = Vg + (size_t)it * 64 * NL;
        #pragma unroll
        for (int i = 0; i < 4; i++) {
            int f4 = tid + i * 256;
            int r  = f4 >> 4;
            int c4 = (f4 & 15) << 2;
            float4 kv = *reinterpret_cast<const float4*>(Kt + (size_t)r * NL + c4);
            uint32_t* d = Ks + r * KSTR + c4;
            d[0] = f2tf(kv.x); d[1] = f2tf(kv.y); d[2] = f2tf(kv.z); d[3] = f2tf(kv.w);
            float4 vv = *reinterpret_cast<const float4*>(Vt + (size_t)r * NL + c4);
            uint32_t* e = Vs + r * VSTR + c4;
            e[0] = f2tf(vv.x); e[1] = f2tf(vv.y); e[2] = f2tf(vv.z); e[3] = f2tf(vv.w);
        }
        __syncthreads();

        float s[8][4];
        #pragma unroll
        for (int j = 0; j < 8; j++) {
            s[j][0] = s[j][1] = s[j][2] = s[j][3] = 0.f;
            #pragma unroll
            for (int c = 0; c < 8; c++) {
                uint32_t b0 = Ks[(8*j + g) * KSTR + 8*c + t];
                uint32_t b1 = Ks[(8*j + g) * KSTR + 8*c + t + 4];
                mma_tf32(s[j][0], s[j][1], s[j][2], s[j][3],
                         qa[c][0], qa[c][1], qa[c][2], qa[c][3], b0, b1);
            }
        }

        float mt0 = s[0][0], mt1 = s[0][2];
        #pragma unroll
        for (int j = 0; j < 8; j++) {
            mt0 = fmaxf(mt0, fmaxf(s[j][0], s[j][1]));
            mt1 = fmaxf(mt1, fmaxf(s[j][2], s[j][3]));
        }
        #pragma unroll
        for (int off = 1; off <= 2; off <<= 1) {
            mt0 = fmaxf(mt0, __shfl_xor_sync(0xffffffffu, mt0, off, 4));
            mt1 = fmaxf(mt1, __shfl_xor_sync(0xffffffffu, mt1, off, 4));
        }
        float mn0 = fmaxf(m0, mt0), mn1 = fmaxf(m1, mt1);
        float a0 = fexp2(m0 - mn0), a1 = fexp2(m1 - mn1);
        float ls0 = 0.f, ls1 = 0.f;
        #pragma unroll
        for (int j = 0; j < 8; j++) {
            s[j][0] = fexp2(s[j][0] - mn0); ls0 += s[j][0];
            s[j][1] = fexp2(s[j][1] - mn0); ls0 += s[j][1];
            s[j][2] = fexp2(s[j][2] - mn1); ls1 += s[j][2];
            s[j][3] = fexp2(s[j][3] - mn1); ls1 += s[j][3];
        }
        #pragma unroll
        for (int off = 1; off <= 2; off <<= 1) {
            ls0 += __shfl_xor_sync(0xffffffffu, ls0, off, 4);
            ls1 += __shfl_xor_sync(0xffffffffu, ls1, off, 4);
        }
        l0 = l0 * a0 + ls0; m0 = mn0;
        l1 = l1 * a1 + ls1; m1 = mn1;
        #pragma unroll
        for (int j = 0; j < 8; j++) {
            o[j][0] *= a0; o[j][1] *= a0; o[j][2] *= a1; o[j][3] *= a1;
        }

        #pragma unroll
        for (int j = 0; j < 8; j++) {
            uint32_t* p0 = Pw + g       * PSTR + 8*j + 2*t;
            uint32_t* p1 = Pw + (g + 8) * PSTR + 8*j + 2*t;
            p0[0] = f2tf(s[j][0]); p0[1] = f2tf(s[j][1]);
            p1[0] = f2tf(s[j][2]); p1[1] = f2tf(s[j][3]);
        }
        __syncwarp();

        uint32_t pa[8][4];
        #pragma unroll
        for (int c = 0; c < 8; c++) {
            pa[c][0] = Pw[g       * PSTR + 8*c + t    ];
            pa[c][1] = Pw[(g + 8) * PSTR + 8*c + t    ];
            pa[c][2] = Pw[g       * PSTR + 8*c + t + 4];
            pa[c][3] = Pw[(g + 8) * PSTR + 8*c + t + 4];
        }

        #pragma unroll
        for (int j = 0; j < 8; j++) {
            #pragma unroll
            for (int c = 0; c < 8; c++) {
                uint32_t b0 = Vs[(8*c + t)     * VSTR + 8*j + g];
                uint32_t b1 = Vs[(8*c + t + 4) * VSTR + 8*j + g];
                mma_tf32(o[j][0], o[j][1], o[j][2], o[j][3],
                         pa[c][0], pa[c][1], pa[c][2], pa[c][3], b0, b1);
            }
        }
    }

    {
        int b = bh >> 3, h = bh & 7;
        float inv0 = 1.f / l0, inv1 = 1.f / l1;
        int r0 = qt * 128 + w * 16 + g;
        float* p0 = g_O + ((size_t)(b * NS + r0)     * (NH * NL)) + h * NL;
        float* p1 = g_O + ((size_t)(b * NS + r0 + 8) * (NH * NL)) + h * NL;
        #pragma unroll
        for (int j = 0; j < 8; j++) {
            *reinterpret_cast<float2*>(p0 + 8*j + 2*t) =
                make_float2(o[j][0] * inv0, o[j][1] * inv0);
            *reinterpret_cast<float2*>(p1 + 8*j + 2*t) =
                make_float2(o[j][2] * inv1, o[j][3] * inv1);
        }
    }
}

// ---------------------------------------------------------------------------
// Kernel 3: output projection (FFMA; unchanged)
// ---------------------------------------------------------------------------
__global__ __launch_bounds__(256) void out_kernel(
    const float* __restrict__ Wo, float* __restrict__ out)
{
    __shared__ float As[16][128];
    __shared__ float Bs[16][64];

    int m0  = blockIdx.x * 128;
    int tid = threadIdx.x;
    int tx  = tid & 15, ty = tid >> 4;

    float acc[8][4];
    #pragma unroll
    for (int i = 0; i < 8; i++)
        #pragma unroll
        for (int j = 0; j < 4; j++) acc[i][j] = 0.f;

    for (int k0 = 0; k0 < ND; k0 += 16) {
        #pragma unroll
        for (int it = 0; it < 2; it++) {
            int f4 = tid + it * 256;
            int r  = f4 >> 2;
            int kc = (f4 & 3) << 2;
            float4 v = *reinterpret_cast<const float4*>(
                g_O + (size_t)(m0 + r) * ND + k0 + kc);
            As[kc+0][r] = v.x; As[kc+1][r] = v.y;
            As[kc+2][r] = v.z; As[kc+3][r] = v.w;
        }
        {
            int r = tid >> 4;
            int c = (tid & 15) << 2;
            *reinterpret_cast<float4*>(&Bs[r][c]) =
                *reinterpret_cast<const float4*>(Wo + (size_t)(k0 + r) * NL + c);
        }
        __syncthreads();

        #pragma unroll
        for (int kk = 0; kk < 16; kk++) {
            float a[8], b[4];
            *reinterpret_cast<float4*>(&a[0]) = *reinterpret_cast<float4*>(&As[kk][ty*8]);
            *reinterpret_cast<float4*>(&a[4]) = *reinterpret_cast<float4*>(&As[kk][ty*8+4]);
            *reinterpret_cast<float4*>(&b[0]) = *reinterpret_cast<float4*>(&Bs[kk][tx*4]);
            #pragma unroll
            for (int i = 0; i < 8; i++)
                #pragma unroll
                for (int j = 0; j < 4; j++)
                    acc[i][j] += a[i] * b[j];
        }
        __syncthreads();
    }

    #pragma unroll
    for (int i = 0; i < 8; i++) {
        int m = m0 + ty * 8 + i;
        float* p = out + (size_t)m * NL + (tx << 2);
        *reinterpret_cast<float4*>(p) =
            make_float4(acc[i][0], acc[i][1], acc[i][2], acc[i][3]);
    }
}

// ---------------------------------------------------------------------------
extern "C" void kernel_launch(void* const* d_in, const int* in_sizes, int n_in,
                              void* d_out, int out_size)
{
    const float* x  = (const float*)d_in[0];
    const float* WQ = (const float*)d_in[1];
    const float* WK = (const float*)d_in[2];
    const float* WV = (const float*)d_in[3];
    const float* WO = (const float*)d_in[4];
    float* out = (float*)d_out;

    cudaFuncSetAttribute(proj_mma, cudaFuncAttributeMaxDynamicSharedMemorySize,
                         PROJ_SMEM);
    proj_mma<<<dim3(128, 8), 256, PROJ_SMEM>>>(x, WQ, WK, WV);

    cudaFuncSetAttribute(attn_mma, cudaFuncAttributeMaxDynamicSharedMemorySize,
                         ATTN_SMEM);
    attn_mma<<<NB * NH * (NS / 128), 256, ATTN_SMEM>>>();

    out_kernel<<<128, 256>>>(WO, out);
}

// round 8
// speedup vs baseline: 3.9833x; 1.3186x over previous
#include <cuda_runtime.h>
#include <cuda_fp16.h>
#include <cstdint>

#define NB 8
#define NS 2048
#define ND 512
#define NH 8
#define NL 64   // LAT == OUT == 64

// Scratch (allocation-free rule: __device__ globals)
__device__ float g_Q[NB*NH*NS*NL];     // [b][h][s][lat]
__device__ float g_K[NB*NH*NS*NL];
__device__ float g_V[NB*NH*NS*NL];
__device__ float g_O[NB*NS*NH*NL];     // [b][s][h*64+o] (head-concat layout)

// ===========================================================================
// helpers
// ===========================================================================
__device__ __forceinline__ uint32_t f2tf(float f) {
    uint32_t u;
    asm("cvt.rna.tf32.f32 %0, %1;" : "=r"(u) : "f"(f));
    return u;
}
__device__ __forceinline__ float fexp2(float x) {
    float r;
    asm("ex2.approx.ftz.f32 %0, %1;" : "=f"(r) : "f"(x));
    return r;
}
__device__ __forceinline__ uint32_t pack_h2(float a, float b) {
    __half2 h = __floats2half2_rn(a, b);
    return *reinterpret_cast<uint32_t*>(&h);
}
// D += A*B, m16n8k8 tf32
__device__ __forceinline__ void mma_tf32(
    float& d0, float& d1, float& d2, float& d3,
    uint32_t a0, uint32_t a1, uint32_t a2, uint32_t a3,
    uint32_t b0, uint32_t b1)
{
    asm volatile(
        "mma.sync.aligned.m16n8k8.row.col.f32.tf32.tf32.f32 "
        "{%0,%1,%2,%3}, {%4,%5,%6,%7}, {%8,%9}, {%0,%1,%2,%3};\n"
        : "+f"(d0), "+f"(d1), "+f"(d2), "+f"(d3)
        : "r"(a0), "r"(a1), "r"(a2), "r"(a3), "r"(b0), "r"(b1));
}
// D += A*B, m16n8k16 fp16 with fp32 accumulate
__device__ __forceinline__ void mma_f16(
    float& d0, float& d1, float& d2, float& d3,
    uint32_t a0, uint32_t a1, uint32_t a2, uint32_t a3,
    uint32_t b0, uint32_t b1)
{
    asm volatile(
        "mma.sync.aligned.m16n8k16.row.col.f32.f16.f16.f32 "
        "{%0,%1,%2,%3}, {%4,%5,%6,%7}, {%8,%9}, {%0,%1,%2,%3};\n"
        : "+f"(d0), "+f"(d1), "+f"(d2), "+f"(d3)
        : "r"(a0), "r"(a1), "r"(a2), "r"(a3), "r"(b0), "r"(b1));
}

// ---------------------------------------------------------------------------
// Kernel 1: fused QKV projections on mma.sync tf32. (unchanged from R6)
// ---------------------------------------------------------------------------
#define XSTR 68
#define WSTR 72
#define PROJ_SMEM ((128*XSTR + 3*64*WSTR) * 4)

__global__ __launch_bounds__(256) void proj_mma(
    const float* __restrict__ x, const float* __restrict__ WQ,
    const float* __restrict__ WK, const float* __restrict__ WV)
{
    extern __shared__ uint32_t psm[];
    uint32_t* Xs = psm;
    uint32_t* Ws = psm + 128 * XSTR;

    int tid  = threadIdx.x;
    int w    = tid >> 5;
    int lane = tid & 31;
    int g    = lane >> 2;
    int t    = lane & 3;

    int h  = blockIdx.y;
    int m0 = blockIdx.x * 128;
    const float* W0 = WQ + (size_t)h * ND * NL;
    const float* W1 = WK + (size_t)h * ND * NL;
    const float* W2 = WV + (size_t)h * ND * NL;

    float o[3][8][4];
    #pragma unroll
    for (int u = 0; u < 3; u++)
        #pragma unroll
        for (int j = 0; j < 8; j++)
            #pragma unroll
            for (int i = 0; i < 4; i++) o[u][j][i] = 0.f;

    for (int k0 = 0; k0 < ND; k0 += 64) {
        __syncthreads();
        #pragma unroll
        for (int i = 0; i < 8; i++) {
            int f4 = tid + i * 256;
            int r  = f4 >> 4;
            int c4 = (f4 & 15) << 2;
            float4 v = *reinterpret_cast<const float4*>(
                x + (size_t)(m0 + r) * ND + k0 + c4);
            uint32_t* d = Xs + r * XSTR + c4;
            d[0]=f2tf(v.x); d[1]=f2tf(v.y); d[2]=f2tf(v.z); d[3]=f2tf(v.w);
        }
        #pragma unroll
        for (int u = 0; u < 3; u++) {
            const float* Wg = (u == 0 ? W0 : u == 1 ? W1 : W2);
            #pragma unroll
            for (int i = 0; i < 4; i++) {
                int f4 = tid + i * 256;
                int r  = f4 >> 4;
                int c4 = (f4 & 15) << 2;
                float4 v = *reinterpret_cast<const float4*>(
                    Wg + (size_t)(k0 + r) * NL + c4);
                uint32_t* d = Ws + u * 64 * WSTR + r * WSTR + c4;
                d[0]=f2tf(v.x); d[1]=f2tf(v.y); d[2]=f2tf(v.z); d[3]=f2tf(v.w);
            }
        }
        __syncthreads();

        #pragma unroll
        for (int c = 0; c < 8; c++) {
            uint32_t a0 = Xs[(16*w + g)     * XSTR + 8*c + t    ];
            uint32_t a1 = Xs[(16*w + g + 8) * XSTR + 8*c + t    ];
            uint32_t a2 = Xs[(16*w + g)     * XSTR + 8*c + t + 4];
            uint32_t a3 = Xs[(16*w + g + 8) * XSTR + 8*c + t + 4];
            #pragma unroll
            for (int u = 0; u < 3; u++) {
                const uint32_t* Wu = Ws + u * 64 * WSTR;
                #pragma unroll
                for (int j = 0; j < 8; j++) {
                    uint32_t b0 = Wu[(8*c + t)     * WSTR + 8*j + g];
                    uint32_t b1 = Wu[(8*c + t + 4) * WSTR + 8*j + g];
                    mma_tf32(o[u][j][0], o[u][j][1], o[u][j][2], o[u][j][3],
                             a0, a1, a2, a3, b0, b1);
                }
            }
        }
    }

    int m = m0 + 16 * w + g;
    int b = m >> 11, s = m & 2047;
    size_t base0 = (((size_t)b * NH + h) * NS + s)     << 6;
    size_t base1 = (((size_t)b * NH + h) * NS + s + 8) << 6;
    #pragma unroll
    for (int u = 0; u < 3; u++) {
        float* dst = (u == 0 ? g_Q : u == 1 ? g_K : g_V);
        #pragma unroll
        for (int j = 0; j < 8; j++) {
            *reinterpret_cast<float2*>(dst + base0 + 8*j + 2*t) =
                make_float2(o[u][j][0], o[u][j][1]);
            *reinterpret_cast<float2*>(dst + base1 + 8*j + 2*t) =
                make_float2(o[u][j][2], o[u][j][3]);
        }
    }
}

// ---------------------------------------------------------------------------
// Kernel 2: flash attention on mma.sync fp16 m16n8k16 (fp32 accumulate).
// CTA = (b, h, 128 q rows). 8 warps; warp w owns q rows [16w,16w+16).
// kv tiles of 64, 32 iterations.
// SMEM (halves):
//   Ksh[64][72]        K tile (row kv, col lat)
//   Vth[64][72]        V^T tile (row out, col kv)   <- transposed at staging
//   Ph [8][16][72]     per-warp P staging (row q, col kv)
// ---------------------------------------------------------------------------
#define KSTRh 72
#define VSTRh 72
#define PSTRh 72
#define ATTN_SMEM ((64*KSTRh + 64*VSTRh + 8*16*PSTRh) * 2)

__global__ __launch_bounds__(256, 2) void attn_mma()
{
    extern __shared__ __half hsm[];
    __half* Ksh = hsm;                    // 64*KSTRh
    __half* Vth = Ksh + 64 * KSTRh;       // 64*VSTRh
    __half* Ph  = Vth + 64 * VSTRh;       // 8*16*PSTRh

    int tid  = threadIdx.x;
    int w    = tid >> 5;
    int lane = tid & 31;
    int g    = lane >> 2;
    int t    = lane & 3;
    __half* Pw = Ph + w * 16 * PSTRh;

    int bh = blockIdx.x >> 4;
    int qt = blockIdx.x & 15;
    const float* Qg = g_Q + (size_t)bh * NS * NL + (size_t)(qt * 128 + w * 16) * NL;
    const float* Kg = g_K + (size_t)bh * NS * NL;
    const float* Vg = g_V + (size_t)bh * NS * NL;

    const float sc = 0.125f * 1.44269504088896340736f;  // (1/sqrt(64))*log2(e)

    // ---- Q fragments fp16 (k-chunks of 16 lat), pre-scaled ----
    uint32_t qa[4][4];
    #pragma unroll
    for (int c = 0; c < 4; c++) {
        const float* r0 = Qg + (size_t)g       * NL + 16*c;
        const float* r1 = Qg + (size_t)(g + 8) * NL + 16*c;
        qa[c][0] = pack_h2(r0[2*t    ] * sc, r0[2*t + 1] * sc);
        qa[c][1] = pack_h2(r1[2*t    ] * sc, r1[2*t + 1] * sc);
        qa[c][2] = pack_h2(r0[2*t + 8] * sc, r0[2*t + 9] * sc);
        qa[c][3] = pack_h2(r1[2*t + 8] * sc, r1[2*t + 9] * sc);
    }

    float o[8][4];
    #pragma unroll
    for (int j = 0; j < 8; j++)
        #pragma unroll
        for (int i = 0; i < 4; i++) o[j][i] = 0.f;
    float m0 = -1e30f, m1 = -1e30f, l0 = 0.f, l1 = 0.f;

    for (int it = 0; it < NS / 64; it++) {
        __syncthreads();
        const float* Kt = Kg + (size_t)it * 64 * NL;
        const float* Vt = Vg + (size_t)it * 64 * NL;
        #pragma unroll
        for (int i = 0; i < 4; i++) {
            int f4 = tid + i * 256;
            int r  = f4 >> 4;
            int c4 = (f4 & 15) << 2;
            float4 kv = *reinterpret_cast<const float4*>(Kt + (size_t)r * NL + c4);
            *reinterpret_cast<uint32_t*>(&Ksh[r * KSTRh + c4    ]) = pack_h2(kv.x, kv.y);
            *reinterpret_cast<uint32_t*>(&Ksh[r * KSTRh + c4 + 2]) = pack_h2(kv.z, kv.w);
            float4 vv = *reinterpret_cast<const float4*>(Vt + (size_t)r * NL + c4);
            // transpose: Vth[out][kv]
            Vth[(c4 + 0) * VSTRh + r] = __float2half_rn(vv.x);
            Vth[(c4 + 1) * VSTRh + r] = __float2half_rn(vv.y);
            Vth[(c4 + 2) * VSTRh + r] = __float2half_rn(vv.z);
            Vth[(c4 + 3) * VSTRh + r] = __float2half_rn(vv.w);
        }
        __syncthreads();

        // ---- S = Q K^T : 8 n-tiles (kv), 4 k-chunks (lat 16 each) ----
        float s[8][4];
        #pragma unroll
        for (int j = 0; j < 8; j++) {
            s[j][0] = s[j][1] = s[j][2] = s[j][3] = 0.f;
            const __half* Kr = Ksh + (8*j + g) * KSTRh;
            #pragma unroll
            for (int c = 0; c < 4; c++) {
                uint32_t b0 = *reinterpret_cast<const uint32_t*>(Kr + 16*c + 2*t    );
                uint32_t b1 = *reinterpret_cast<const uint32_t*>(Kr + 16*c + 2*t + 8);
                mma_f16(s[j][0], s[j][1], s[j][2], s[j][3],
                        qa[c][0], qa[c][1], qa[c][2], qa[c][3], b0, b1);
            }
        }

        // ---- online softmax (rows g and g+8; quad = lanes sharing a row) ----
        float mt0 = s[0][0], mt1 = s[0][2];
        #pragma unroll
        for (int j = 0; j < 8; j++) {
            mt0 = fmaxf(mt0, fmaxf(s[j][0], s[j][1]));
            mt1 = fmaxf(mt1, fmaxf(s[j][2], s[j][3]));
        }
        #pragma unroll
        for (int off = 1; off <= 2; off <<= 1) {
            mt0 = fmaxf(mt0, __shfl_xor_sync(0xffffffffu, mt0, off, 4));
            mt1 = fmaxf(mt1, __shfl_xor_sync(0xffffffffu, mt1, off, 4));
        }
        float mn0 = fmaxf(m0, mt0), mn1 = fmaxf(m1, mt1);
        float a0 = fexp2(m0 - mn0), a1 = fexp2(m1 - mn1);
        float ls0 = 0.f, ls1 = 0.f;
        #pragma unroll
        for (int j = 0; j < 8; j++) {
            s[j][0] = fexp2(s[j][0] - mn0); ls0 += s[j][0];
            s[j][1] = fexp2(s[j][1] - mn0); ls0 += s[j][1];
            s[j][2] = fexp2(s[j][2] - mn1); ls1 += s[j][2];
            s[j][3] = fexp2(s[j][3] - mn1); ls1 += s[j][3];
        }
        #pragma unroll
        for (int off = 1; off <= 2; off <<= 1) {
            ls0 += __shfl_xor_sync(0xffffffffu, ls0, off, 4);
            ls1 += __shfl_xor_sync(0xffffffffu, ls1, off, 4);
        }
        l0 = l0 * a0 + ls0; m0 = mn0;
        l1 = l1 * a1 + ls1; m1 = mn1;
        #pragma unroll
        for (int j = 0; j < 8; j++) {
            o[j][0] *= a0; o[j][1] *= a0; o[j][2] *= a1; o[j][3] *= a1;
        }

        // ---- stage P (fp16) in per-warp smem: C-layout -> row-major ----
        #pragma unroll
        for (int j = 0; j < 8; j++) {
            *reinterpret_cast<uint32_t*>(Pw + g       * PSTRh + 8*j + 2*t) =
                pack_h2(s[j][0], s[j][1]);
            *reinterpret_cast<uint32_t*>(Pw + (g + 8) * PSTRh + 8*j + 2*t) =
                pack_h2(s[j][2], s[j][3]);
        }
        __syncwarp();

        // ---- A-fragments of P (k = kv, 4 chunks of 16) ----
        uint32_t pa[4][4];
        #pragma unroll
        for (int c = 0; c < 4; c++) {
            const __half* p0 = Pw + g       * PSTRh + 16*c;
            const __half* p1 = Pw + (g + 8) * PSTRh + 16*c;
            pa[c][0] = *reinterpret_cast<const uint32_t*>(p0 + 2*t    );
            pa[c][1] = *reinterpret_cast<const uint32_t*>(p1 + 2*t    );
            pa[c][2] = *reinterpret_cast<const uint32_t*>(p0 + 2*t + 8);
            pa[c][3] = *reinterpret_cast<const uint32_t*>(p1 + 2*t + 8);
        }

        // ---- O += P V : 8 n-tiles (out), 4 k-chunks (kv 16 each) ----
        #pragma unroll
        for (int j = 0; j < 8; j++) {
            const __half* Vr = Vth + (8*j + g) * VSTRh;
            #pragma unroll
            for (int c = 0; c < 4; c++) {
                uint32_t b0 = *reinterpret_cast<const uint32_t*>(Vr + 16*c + 2*t    );
                uint32_t b1 = *reinterpret_cast<const uint32_t*>(Vr + 16*c + 2*t + 8);
                mma_f16(o[j][0], o[j][1], o[j][2], o[j][3],
                        pa[c][0], pa[c][1], pa[c][2], pa[c][3], b0, b1);
            }
        }
    }

    // ---- normalize + write head-concat layout [b][s][h*64+o] ----
    {
        int b = bh >> 3, h = bh & 7;
        float inv0 = 1.f / l0, inv1 = 1.f / l1;
        int r0 = qt * 128 + w * 16 + g;
        float* p0 = g_O + ((size_t)(b * NS + r0)     * (NH * NL)) + h * NL;
        float* p1 = g_O + ((size_t)(b * NS + r0 + 8) * (NH * NL)) + h * NL;
        #pragma unroll
        for (int j = 0; j < 8; j++) {
            *reinterpret_cast<float2*>(p0 + 8*j + 2*t) =
                make_float2(o[j][0] * inv0, o[j][1] * inv0);
            *reinterpret_cast<float2*>(p1 + 8*j + 2*t) =
                make_float2(o[j][2] * inv1, o[j][3] * inv1);
        }
    }
}

// ---------------------------------------------------------------------------
// Kernel 3: output projection (FFMA; unchanged)
// ---------------------------------------------------------------------------
__global__ __launch_bounds__(256) void out_kernel(
    const float* __restrict__ Wo, float* __restrict__ out)
{
    __shared__ float As[16][128];
    __shared__ float Bs[16][64];

    int m0  = blockIdx.x * 128;
    int tid = threadIdx.x;
    int tx  = tid & 15, ty = tid >> 4;

    float acc[8][4];
    #pragma unroll
    for (int i = 0; i < 8; i++)
        #pragma unroll
        for (int j = 0; j < 4; j++) acc[i][j] = 0.f;

    for (int k0 = 0; k0 < ND; k0 += 16) {
        #pragma unroll
        for (int it = 0; it < 2; it++) {
            int f4 = tid + it * 256;
            int r  = f4 >> 2;
            int kc = (f4 & 3) << 2;
            float4 v = *reinterpret_cast<const float4*>(
                g_O + (size_t)(m0 + r) * ND + k0 + kc);
            As[kc+0][r] = v.x; As[kc+1][r] = v.y;
            As[kc+2][r] = v.z; As[kc+3][r] = v.w;
        }
        {
            int r = tid >> 4;
            int c = (tid & 15) << 2;
            *reinterpret_cast<float4*>(&Bs[r][c]) =
                *reinterpret_cast<const float4*>(Wo + (size_t)(k0 + r) * NL + c);
        }
        __syncthreads();

        #pragma unroll
        for (int kk = 0; kk < 16; kk++) {
            float a[8], b[4];
            *reinterpret_cast<float4*>(&a[0]) = *reinterpret_cast<float4*>(&As[kk][ty*8]);
            *reinterpret_cast<float4*>(&a[4]) = *reinterpret_cast<float4*>(&As[kk][ty*8+4]);
            *reinterpret_cast<float4*>(&b[0]) = *reinterpret_cast<float4*>(&Bs[kk][tx*4]);
            #pragma unroll
            for (int i = 0; i < 8; i++)
                #pragma unroll
                for (int j = 0; j < 4; j++)
                    acc[i][j] += a[i] * b[j];
        }
        __syncthreads();
    }

    #pragma unroll
    for (int i = 0; i < 8; i++) {
        int m = m0 + ty * 8 + i;
        float* p = out + (size_t)m * NL + (tx << 2);
        *reinterpret_cast<float4*>(p) =
            make_float4(acc[i][0], acc[i][1], acc[i][2], acc[i][3]);
    }
}

// ---------------------------------------------------------------------------
extern "C" void kernel_launch(void* const* d_in, const int* in_sizes, int n_in,
                              void* d_out, int out_size)
{
    const float* x  = (const float*)d_in[0];
    const float* WQ = (const float*)d_in[1];
    const float* WK = (const float*)d_in[2];
    const float* WV = (const float*)d_in[3];
    const float* WO = (const float*)d_in[4];
    float* out = (float*)d_out;

    cudaFuncSetAttribute(proj_mma, cudaFuncAttributeMaxDynamicSharedMemorySize,
                         PROJ_SMEM);
    proj_mma<<<dim3(128, 8), 256, PROJ_SMEM>>>(x, WQ, WK, WV);

    cudaFuncSetAttribute(attn_mma, cudaFuncAttributeMaxDynamicSharedMemorySize,
                         ATTN_SMEM);
    attn_mma<<<NB * NH * (NS / 128), 256, ATTN_SMEM>>>();

    out_kernel<<<128, 256>>>(WO, out);
}

// round 9
// speedup vs baseline: 4.1489x; 1.0416x over previous
#include <cuda_runtime.h>
#include <cuda_fp16.h>
#include <cstdint>

#define NB 8
#define NS 2048
#define ND 512
#define NH 8
#define NL 64   // LAT == OUT == 64

// Scratch (allocation-free rule: __device__ globals)
__device__ float g_Q[NB*NH*NS*NL];     // [b][h][s][lat]
__device__ float g_K[NB*NH*NS*NL];
__device__ float g_V[NB*NH*NS*NL];
__device__ float g_O[NB*NS*NH*NL];     // [b][s][h*64+o] (head-concat layout)

// ===========================================================================
// helpers
// ===========================================================================
__device__ __forceinline__ float fexp2(float x) {
    float r;
    asm("ex2.approx.ftz.f32 %0, %1;" : "=f"(r) : "f"(x));
    return r;
}
__device__ __forceinline__ uint32_t pack_h2(float a, float b) {
    __half2 h = __floats2half2_rn(a, b);
    return *reinterpret_cast<uint32_t*>(&h);
}
// D += A*B, m16n8k16 fp16 with fp32 accumulate
__device__ __forceinline__ void mma_f16(
    float& d0, float& d1, float& d2, float& d3,
    uint32_t a0, uint32_t a1, uint32_t a2, uint32_t a3,
    uint32_t b0, uint32_t b1)
{
    asm volatile(
        "mma.sync.aligned.m16n8k16.row.col.f32.f16.f16.f32 "
        "{%0,%1,%2,%3}, {%4,%5,%6,%7}, {%8,%9}, {%0,%1,%2,%3};\n"
        : "+f"(d0), "+f"(d1), "+f"(d2), "+f"(d3)
        : "r"(a0), "r"(a1), "r"(a2), "r"(a3), "r"(b0), "r"(b1));
}

// ---------------------------------------------------------------------------
// Kernel 1: fused QKV projections on mma.sync fp16 (fp32 accumulate).
// Grid (128 row-tiles, 8 heads). CTA computes Q,K,V [128 x 64] for one head.
// 8 warps, warp w owns rows [16w,16w+16). Accumulators o[3][8][4] (fp32).
//   Xh[128][72] halves (row-major, k pairs packed)   a-frag: bank 4g+t
//   Wt[3][64][70] halves (n-major, k pairs packed)   b-frag: bank ~3g+t
// W transposed at staging via xor-16 shuffle (lane pairs hold rows k, k+1).
// ---------------------------------------------------------------------------
#define XSh 72
#define WSh 70
#define PROJ_SMEM ((128*XSh + 3*64*WSh) * 2)

__global__ __launch_bounds__(256, 2) void proj_mma(
    const float* __restrict__ x, const float* __restrict__ WQ,
    const float* __restrict__ WK, const float* __restrict__ WV)
{
    extern __shared__ __half psm[];
    __half* Xh = psm;               // 128*XSh
    __half* Wt = psm + 128 * XSh;   // 3 * 64*WSh   (n-major)

    int tid  = threadIdx.x;
    int w    = tid >> 5;
    int lane = tid & 31;
    int g    = lane >> 2;
    int t    = lane & 3;

    int h  = blockIdx.y;
    int m0 = blockIdx.x * 128;
    const float* W0 = WQ + (size_t)h * ND * NL;
    const float* W1 = WK + (size_t)h * ND * NL;
    const float* W2 = WV + (size_t)h * ND * NL;

    float o[3][8][4];
    #pragma unroll
    for (int u = 0; u < 3; u++)
        #pragma unroll
        for (int j = 0; j < 8; j++)
            #pragma unroll
            for (int i = 0; i < 4; i++) o[u][j][i] = 0.f;

    for (int k0 = 0; k0 < ND; k0 += 64) {
        __syncthreads();
        // ---- X tile [128,64] -> halves, row-major ----
        #pragma unroll
        for (int i = 0; i < 8; i++) {
            int f4 = tid + i * 256;
            int r  = f4 >> 4;            // 0..127
            int c4 = (f4 & 15) << 2;
            float4 v = *reinterpret_cast<const float4*>(
                x + (size_t)(m0 + r) * ND + k0 + c4);
            *reinterpret_cast<uint32_t*>(&Xh[r * XSh + c4    ]) = pack_h2(v.x, v.y);
            *reinterpret_cast<uint32_t*>(&Xh[r * XSh + c4 + 2]) = pack_h2(v.z, v.w);
        }
        // ---- W tiles [64k,64n] x3 -> transposed halves Wt[n][k] ----
        // lanes l and l^16 hold rows R (even) and R+1 of the same c4 columns.
        #pragma unroll
        for (int u = 0; u < 3; u++) {
            const float* Wg = (u == 0 ? W0 : u == 1 ? W1 : W2);
            __half* Wu = Wt + u * 64 * WSh;
            #pragma unroll
            for (int i = 0; i < 4; i++) {
                int f4 = tid + i * 256;
                int r  = f4 >> 4;        // 0..63; lanes<16 -> R, >=16 -> R+1
                int c4 = (f4 & 15) << 2;
                float4 v = *reinterpret_cast<const float4*>(
                    Wg + (size_t)(k0 + r) * NL + c4);
                float4 p;
                p.x = __shfl_xor_sync(0xffffffffu, v.x, 16);
                p.y = __shfl_xor_sync(0xffffffffu, v.y, 16);
                p.z = __shfl_xor_sync(0xffffffffu, v.z, 16);
                p.w = __shfl_xor_sync(0xffffffffu, v.w, 16);
                if (lane < 16) {
                    int R = r;   // even
                    *reinterpret_cast<uint32_t*>(&Wu[(c4    ) * WSh + R]) = pack_h2(v.x, p.x);
                    *reinterpret_cast<uint32_t*>(&Wu[(c4 + 1) * WSh + R]) = pack_h2(v.y, p.y);
                } else {
                    int R = r - 1;
                    *reinterpret_cast<uint32_t*>(&Wu[(c4 + 2) * WSh + R]) = pack_h2(p.z, v.z);
                    *reinterpret_cast<uint32_t*>(&Wu[(c4 + 3) * WSh + R]) = pack_h2(p.w, v.w);
                }
            }
        }
        __syncthreads();

        // ---- MMA: 4 k-chunks of 16; n-tiles j=0..7; outputs u=0..2 ----
        #pragma unroll
        for (int c = 0; c < 4; c++) {
            const __half* Xr0 = Xh + (16*w + g)     * XSh + 16*c;
            const __half* Xr1 = Xh + (16*w + g + 8) * XSh + 16*c;
            uint32_t a0 = *reinterpret_cast<const uint32_t*>(Xr0 + 2*t    );
            uint32_t a1 = *reinterpret_cast<const uint32_t*>(Xr1 + 2*t    );
            uint32_t a2 = *reinterpret_cast<const uint32_t*>(Xr0 + 2*t + 8);
            uint32_t a3 = *reinterpret_cast<const uint32_t*>(Xr1 + 2*t + 8);
            #pragma unroll
            for (int u = 0; u < 3; u++) {
                const __half* Wu = Wt + u * 64 * WSh;
                #pragma unroll
                for (int j = 0; j < 8; j++) {
                    const __half* Wr = Wu + (8*j + g) * WSh + 16*c;
                    uint32_t b0 = *reinterpret_cast<const uint32_t*>(Wr + 2*t    );
                    uint32_t b1 = *reinterpret_cast<const uint32_t*>(Wr + 2*t + 8);
                    mma_f16(o[u][j][0], o[u][j][1], o[u][j][2], o[u][j][3],
                            a0, a1, a2, a3, b0, b1);
                }
            }
        }
    }

    // write to [b][h][s][64]
    int m = m0 + 16 * w + g;
    int b = m >> 11, s = m & 2047;
    size_t base0 = (((size_t)b * NH + h) * NS + s)     << 6;
    size_t base1 = (((size_t)b * NH + h) * NS + s + 8) << 6;
    #pragma unroll
    for (int u = 0; u < 3; u++) {
        float* dst = (u == 0 ? g_Q : u == 1 ? g_K : g_V);
        #pragma unroll
        for (int j = 0; j < 8; j++) {
            *reinterpret_cast<float2*>(dst + base0 + 8*j + 2*t) =
                make_float2(o[u][j][0], o[u][j][1]);
            *reinterpret_cast<float2*>(dst + base1 + 8*j + 2*t) =
                make_float2(o[u][j][2], o[u][j][3]);
        }
    }
}

// ---------------------------------------------------------------------------
// Kernel 2: flash attention on mma.sync fp16 m16n8k16. (unchanged from R8)
// ---------------------------------------------------------------------------
#define KSTRh 72
#define VSTRh 72
#define PSTRh 72
#define ATTN_SMEM ((64*KSTRh + 64*VSTRh + 8*16*PSTRh) * 2)

__global__ __launch_bounds__(256, 2) void attn_mma()
{
    extern __shared__ __half hsm[];
    __half* Ksh = hsm;
    __half* Vth = Ksh + 64 * KSTRh;
    __half* Ph  = Vth + 64 * VSTRh;

    int tid  = threadIdx.x;
    int w    = tid >> 5;
    int lane = tid & 31;
    int g    = lane >> 2;
    int t    = lane & 3;
    __half* Pw = Ph + w * 16 * PSTRh;

    int bh = blockIdx.x >> 4;
    int qt = blockIdx.x & 15;
    const float* Qg = g_Q + (size_t)bh * NS * NL + (size_t)(qt * 128 + w * 16) * NL;
    const float* Kg = g_K + (size_t)bh * NS * NL;
    const float* Vg = g_V + (size_t)bh * NS * NL;

    const float sc = 0.125f * 1.44269504088896340736f;

    uint32_t qa[4][4];
    #pragma unroll
    for (int c = 0; c < 4; c++) {
        const float* r0 = Qg + (size_t)g       * NL + 16*c;
        const float* r1 = Qg + (size_t)(g + 8) * NL + 16*c;
        qa[c][0] = pack_h2(r0[2*t    ] * sc, r0[2*t + 1] * sc);
        qa[c][1] = pack_h2(r1[2*t    ] * sc, r1[2*t + 1] * sc);
        qa[c][2] = pack_h2(r0[2*t + 8] * sc, r0[2*t + 9] * sc);
        qa[c][3] = pack_h2(r1[2*t + 8] * sc, r1[2*t + 9] * sc);
    }

    float o[8][4];
    #pragma unroll
    for (int j = 0; j < 8; j++)
        #pragma unroll
        for (int i = 0; i < 4; i++) o[j][i] = 0.f;
    float m0 = -1e30f, m1 = -1e30f, l0 = 0.f, l1 = 0.f;

    for (int it = 0; it < NS / 64; it++) {
        __syncthreads();
        const float* Kt = Kg + (size_t)it * 64 * NL;
        const float* Vt = Vg + (size_t)it * 64 * NL;
        #pragma unroll
        for (int i = 0; i < 4; i++) {
            int f4 = tid + i * 256;
            int r  = f4 >> 4;
            int c4 = (f4 & 15) << 2;
            float4 kv = *reinterpret_cast<const float4*>(Kt + (size_t)r * NL + c4);
            *reinterpret_cast<uint32_t*>(&Ksh[r * KSTRh + c4    ]) = pack_h2(kv.x, kv.y);
            *reinterpret_cast<uint32_t*>(&Ksh[r * KSTRh + c4 + 2]) = pack_h2(kv.z, kv.w);
            float4 vv = *reinterpret_cast<const float4*>(Vt + (size_t)r * NL + c4);
            Vth[(c4 + 0) * VSTRh + r] = __float2half_rn(vv.x);
            Vth[(c4 + 1) * VSTRh + r] = __float2half_rn(vv.y);
            Vth[(c4 + 2) * VSTRh + r] = __float2half_rn(vv.z);
            Vth[(c4 + 3) * VSTRh + r] = __float2half_rn(vv.w);
        }
        __syncthreads();

        float s[8][4];
        #pragma unroll
        for (int j = 0; j < 8; j++) {
            s[j][0] = s[j][1] = s[j][2] = s[j][3] = 0.f;
            const __half* Kr = Ksh + (8*j + g) * KSTRh;
            #pragma unroll
            for (int c = 0; c < 4; c++) {
                uint32_t b0 = *reinterpret_cast<const uint32_t*>(Kr + 16*c + 2*t    );
                uint32_t b1 = *reinterpret_cast<const uint32_t*>(Kr + 16*c + 2*t + 8);
                mma_f16(s[j][0], s[j][1], s[j][2], s[j][3],
                        qa[c][0], qa[c][1], qa[c][2], qa[c][3], b0, b1);
            }
        }

        float mt0 = s[0][0], mt1 = s[0][2];
        #pragma unroll
        for (int j = 0; j < 8; j++) {
            mt0 = fmaxf(mt0, fmaxf(s[j][0], s[j][1]));
            mt1 = fmaxf(mt1, fmaxf(s[j][2], s[j][3]));
        }
        #pragma unroll
        for (int off = 1; off <= 2; off <<= 1) {
            mt0 = fmaxf(mt0, __shfl_xor_sync(0xffffffffu, mt0, off, 4));
            mt1 = fmaxf(mt1, __shfl_xor_sync(0xffffffffu, mt1, off, 4));
        }
        float mn0 = fmaxf(m0, mt0), mn1 = fmaxf(m1, mt1);
        float a0 = fexp2(m0 - mn0), a1 = fexp2(m1 - mn1);
        float ls0 = 0.f, ls1 = 0.f;
        #pragma unroll
        for (int j = 0; j < 8; j++) {
            s[j][0] = fexp2(s[j][0] - mn0); ls0 += s[j][0];
            s[j][1] = fexp2(s[j][1] - mn0); ls0 += s[j][1];
            s[j][2] = fexp2(s[j][2] - mn1); ls1 += s[j][2];
            s[j][3] = fexp2(s[j][3] - mn1); ls1 += s[j][3];
        }
        #pragma unroll
        for (int off = 1; off <= 2; off <<= 1) {
            ls0 += __shfl_xor_sync(0xffffffffu, ls0, off, 4);
            ls1 += __shfl_xor_sync(0xffffffffu, ls1, off, 4);
        }
        l0 = l0 * a0 + ls0; m0 = mn0;
        l1 = l1 * a1 + ls1; m1 = mn1;
        #pragma unroll
        for (int j = 0; j < 8; j++) {
            o[j][0] *= a0; o[j][1] *= a0; o[j][2] *= a1; o[j][3] *= a1;
        }

        #pragma unroll
        for (int j = 0; j < 8; j++) {
            *reinterpret_cast<uint32_t*>(Pw + g       * PSTRh + 8*j + 2*t) =
                pack_h2(s[j][0], s[j][1]);
            *reinterpret_cast<uint32_t*>(Pw + (g + 8) * PSTRh + 8*j + 2*t) =
                pack_h2(s[j][2], s[j][3]);
        }
        __syncwarp();

        uint32_t pa[4][4];
        #pragma unroll
        for (int c = 0; c < 4; c++) {
            const __half* p0 = Pw + g       * PSTRh + 16*c;
            const __half* p1 = Pw + (g + 8) * PSTRh + 16*c;
            pa[c][0] = *reinterpret_cast<const uint32_t*>(p0 + 2*t    );
            pa[c][1] = *reinterpret_cast<const uint32_t*>(p1 + 2*t    );
            pa[c][2] = *reinterpret_cast<const uint32_t*>(p0 + 2*t + 8);
            pa[c][3] = *reinterpret_cast<const uint32_t*>(p1 + 2*t + 8);
        }

        #pragma unroll
        for (int j = 0; j < 8; j++) {
            const __half* Vr = Vth + (8*j + g) * VSTRh;
            #pragma unroll
            for (int c = 0; c < 4; c++) {
                uint32_t b0 = *reinterpret_cast<const uint32_t*>(Vr + 16*c + 2*t    );
                uint32_t b1 = *reinterpret_cast<const uint32_t*>(Vr + 16*c + 2*t + 8);
                mma_f16(o[j][0], o[j][1], o[j][2], o[j][3],
                        pa[c][0], pa[c][1], pa[c][2], pa[c][3], b0, b1);
            }
        }
    }

    {
        int b = bh >> 3, h = bh & 7;
        float inv0 = 1.f / l0, inv1 = 1.f / l1;
        int r0 = qt * 128 + w * 16 + g;
        float* p0 = g_O + ((size_t)(b * NS + r0)     * (NH * NL)) + h * NL;
        float* p1 = g_O + ((size_t)(b * NS + r0 + 8) * (NH * NL)) + h * NL;
        #pragma unroll
        for (int j = 0; j < 8; j++) {
            *reinterpret_cast<float2*>(p0 + 8*j + 2*t) =
                make_float2(o[j][0] * inv0, o[j][1] * inv0);
            *reinterpret_cast<float2*>(p1 + 8*j + 2*t) =
                make_float2(o[j][2] * inv1, o[j][3] * inv1);
        }
    }
}

// ---------------------------------------------------------------------------
// Kernel 3: output projection (FFMA; fp32 kept deliberately for accuracy)
// ---------------------------------------------------------------------------
__global__ __launch_bounds__(256) void out_kernel(
    const float* __restrict__ Wo, float* __restrict__ out)
{
    __shared__ float As[16][128];
    __shared__ float Bs[16][64];

    int m0  = blockIdx.x * 128;
    int tid = threadIdx.x;
    int tx  = tid & 15, ty = tid >> 4;

    float acc[8][4];
    #pragma unroll
    for (int i = 0; i < 8; i++)
        #pragma unroll
        for (int j = 0; j < 4; j++) acc[i][j] = 0.f;

    for (int k0 = 0; k0 < ND; k0 += 16) {
        #pragma unroll
        for (int it = 0; it < 2; it++) {
            int f4 = tid + it * 256;
            int r  = f4 >> 2;
            int kc = (f4 & 3) << 2;
            float4 v = *reinterpret_cast<const float4*>(
                g_O + (size_t)(m0 + r) * ND + k0 + kc);
            As[kc+0][r] = v.x; As[kc+1][r] = v.y;
            As[kc+2][r] = v.z; As[kc+3][r] = v.w;
        }
        {
            int r = tid >> 4;
            int c = (tid & 15) << 2;
            *reinterpret_cast<float4*>(&Bs[r][c]) =
                *reinterpret_cast<const float4*>(Wo + (size_t)(k0 + r) * NL + c);
        }
        __syncthreads();

        #pragma unroll
        for (int kk = 0; kk < 16; kk++) {
            float a[8], b[4];
            *reinterpret_cast<float4*>(&a[0]) = *reinterpret_cast<float4*>(&As[kk][ty*8]);
            *reinterpret_cast<float4*>(&a[4]) = *reinterpret_cast<float4*>(&As[kk][ty*8+4]);
            *reinterpret_cast<float4*>(&b[0]) = *reinterpret_cast<float4*>(&Bs[kk][tx*4]);
            #pragma unroll
            for (int i = 0; i < 8; i++)
                #pragma unroll
                for (int j = 0; j < 4; j++)
                    acc[i][j] += a[i] * b[j];
        }
        __syncthreads();
    }

    #pragma unroll
    for (int i = 0; i < 8; i++) {
        int m = m0 + ty * 8 + i;
        float* p = out + (size_t)m * NL + (tx << 2);
        *reinterpret_cast<float4*>(p) =
            make_float4(acc[i][0], acc[i][1], acc[i][2], acc[i][3]);
    }
}

// ---------------------------------------------------------------------------
extern "C" void kernel_launch(void* const* d_in, const int* in_sizes, int n_in,
                              void* d_out, int out_size)
{
    const float* x  = (const float*)d_in[0];
    const float* WQ = (const float*)d_in[1];
    const float* WK = (const float*)d_in[2];
    const float* WV = (const float*)d_in[3];
    const float* WO = (const float*)d_in[4];
    float* out = (float*)d_out;

    cudaFuncSetAttribute(proj_mma, cudaFuncAttributeMaxDynamicSharedMemorySize,
                         PROJ_SMEM);
    proj_mma<<<dim3(128, 8), 256, PROJ_SMEM>>>(x, WQ, WK, WV);

    cudaFuncSetAttribute(attn_mma, cudaFuncAttributeMaxDynamicSharedMemorySize,
                         ATTN_SMEM);
    attn_mma<<<NB * NH * (NS / 128), 256, ATTN_SMEM>>>();

    out_kernel<<<128, 256>>>(WO, out);
}

// round 11
// speedup vs baseline: 5.3482x; 1.2891x over previous
#include <cuda_runtime.h>
#include <cuda_fp16.h>
#include <cstdint>

#define NB 8
#define NS 2048
#define ND 512
#define NH 8
#define NL 64   // LAT == OUT == 64

// Scratch (allocation-free rule: __device__ globals)
__device__ float g_Q[NB*NH*NS*NL];     // [b][h][s][lat]
__device__ float g_K[NB*NH*NS*NL];
__device__ float g_V[NB*NH*NS*NL];
__device__ float g_O[NB*NS*NH*NL];     // [b][s][h*64+o] (head-concat layout)

// ===========================================================================
// helpers
// ===========================================================================
__device__ __forceinline__ float fexp2(float x) {
    float r;
    asm("ex2.approx.ftz.f32 %0, %1;" : "=f"(r) : "f"(x));
    return r;
}
__device__ __forceinline__ uint32_t pack_h2(float a, float b) {
    __half2 h = __floats2half2_rn(a, b);
    return *reinterpret_cast<uint32_t*>(&h);
}
// D += A*B, m16n8k16 fp16 with fp32 accumulate
__device__ __forceinline__ void mma_f16(
    float& d0, float& d1, float& d2, float& d3,
    uint32_t a0, uint32_t a1, uint32_t a2, uint32_t a3,
    uint32_t b0, uint32_t b1)
{
    asm volatile(
        "mma.sync.aligned.m16n8k16.row.col.f32.f16.f16.f32 "
        "{%0,%1,%2,%3}, {%4,%5,%6,%7}, {%8,%9}, {%0,%1,%2,%3};\n"
        : "+f"(d0), "+f"(d1), "+f"(d2), "+f"(d3)
        : "r"(a0), "r"(a1), "r"(a2), "r"(a3), "r"(b0), "r"(b1));
}
__device__ __forceinline__ void ldm_x4(
    uint32_t& r0, uint32_t& r1, uint32_t& r2, uint32_t& r3, uint32_t addr)
{
    asm volatile("ldmatrix.sync.aligned.m8n8.x4.shared.b16 {%0,%1,%2,%3}, [%4];"
                 : "=r"(r0), "=r"(r1), "=r"(r2), "=r"(r3) : "r"(addr));
}
__device__ __forceinline__ void ldm_x4_t(
    uint32_t& r0, uint32_t& r1, uint32_t& r2, uint32_t& r3, uint32_t addr)
{
    asm volatile("ldmatrix.sync.aligned.m8n8.x4.trans.shared.b16 {%0,%1,%2,%3}, [%4];"
                 : "=r"(r0), "=r"(r1), "=r"(r2), "=r"(r3) : "r"(addr));
}

// ---------------------------------------------------------------------------
// Kernel 1: fused QKV projections on mma.sync fp16. (unchanged from R9)
// ---------------------------------------------------------------------------
#define XSh 72
#define WSh 70
#define PROJ_SMEM ((128*XSh + 3*64*WSh) * 2)

__global__ __launch_bounds__(256, 2) void proj_mma(
    const float* __restrict__ x, const float* __restrict__ WQ,
    const float* __restrict__ WK, const float* __restrict__ WV)
{
    extern __shared__ __half psm[];
    __half* Xh = psm;
    __half* Wt = psm + 128 * XSh;

    int tid  = threadIdx.x;
    int w    = tid >> 5;
    int lane = tid & 31;
    int g    = lane >> 2;
    int t    = lane & 3;

    int h  = blockIdx.y;
    int m0 = blockIdx.x * 128;
    const float* W0 = WQ + (size_t)h * ND * NL;
    const float* W1 = WK + (size_t)h * ND * NL;
    const float* W2 = WV + (size_t)h * ND * NL;

    float o[3][8][4];
    #pragma unroll
    for (int u = 0; u < 3; u++)
        #pragma unroll
        for (int j = 0; j < 8; j++)
            #pragma unroll
            for (int i = 0; i < 4; i++) o[u][j][i] = 0.f;

    for (int k0 = 0; k0 < ND; k0 += 64) {
        __syncthreads();
        #pragma unroll
        for (int i = 0; i < 8; i++) {
            int f4 = tid + i * 256;
            int r  = f4 >> 4;
            int c4 = (f4 & 15) << 2;
            float4 v = *reinterpret_cast<const float4*>(
                x + (size_t)(m0 + r) * ND + k0 + c4);
            *reinterpret_cast<uint32_t*>(&Xh[r * XSh + c4    ]) = pack_h2(v.x, v.y);
            *reinterpret_cast<uint32_t*>(&Xh[r * XSh + c4 + 2]) = pack_h2(v.z, v.w);
        }
        #pragma unroll
        for (int u = 0; u < 3; u++) {
            const float* Wg = (u == 0 ? W0 : u == 1 ? W1 : W2);
            __half* Wu = Wt + u * 64 * WSh;
            #pragma unroll
            for (int i = 0; i < 4; i++) {
                int f4 = tid + i * 256;
                int r  = f4 >> 4;
                int c4 = (f4 & 15) << 2;
                float4 v = *reinterpret_cast<const float4*>(
                    Wg + (size_t)(k0 + r) * NL + c4);
                float4 p;
                p.x = __shfl_xor_sync(0xffffffffu, v.x, 16);
                p.y = __shfl_xor_sync(0xffffffffu, v.y, 16);
                p.z = __shfl_xor_sync(0xffffffffu, v.z, 16);
                p.w = __shfl_xor_sync(0xffffffffu, v.w, 16);
                if (lane < 16) {
                    int R = r;
                    *reinterpret_cast<uint32_t*>(&Wu[(c4    ) * WSh + R]) = pack_h2(v.x, p.x);
                    *reinterpret_cast<uint32_t*>(&Wu[(c4 + 1) * WSh + R]) = pack_h2(v.y, p.y);
                } else {
                    int R = r - 1;
                    *reinterpret_cast<uint32_t*>(&Wu[(c4 + 2) * WSh + R]) = pack_h2(p.z, v.z);
                    *reinterpret_cast<uint32_t*>(&Wu[(c4 + 3) * WSh + R]) = pack_h2(p.w, v.w);
                }
            }
        }
        __syncthreads();

        #pragma unroll
        for (int c = 0; c < 4; c++) {
            const __half* Xr0 = Xh + (16*w + g)     * XSh + 16*c;
            const __half* Xr1 = Xh + (16*w + g + 8) * XSh + 16*c;
            uint32_t a0 = *reinterpret_cast<const uint32_t*>(Xr0 + 2*t    );
            uint32_t a1 = *reinterpret_cast<const uint32_t*>(Xr1 + 2*t    );
            uint32_t a2 = *reinterpret_cast<const uint32_t*>(Xr0 + 2*t + 8);
            uint32_t a3 = *reinterpret_cast<const uint32_t*>(Xr1 + 2*t + 8);
            #pragma unroll
            for (int u = 0; u < 3; u++) {
                const __half* Wu = Wt + u * 64 * WSh;
                #pragma unroll
                for (int j = 0; j < 8; j++) {
                    const __half* Wr = Wu + (8*j + g) * WSh + 16*c;
                    uint32_t b0 = *reinterpret_cast<const uint32_t*>(Wr + 2*t    );
                    uint32_t b1 = *reinterpret_cast<const uint32_t*>(Wr + 2*t + 8);
                    mma_f16(o[u][j][0], o[u][j][1], o[u][j][2], o[u][j][3],
                            a0, a1, a2, a3, b0, b1);
                }
            }
        }
    }

    int m = m0 + 16 * w + g;
    int b = m >> 11, s = m & 2047;
    size_t base0 = (((size_t)b * NH + h) * NS + s)     << 6;
    size_t base1 = (((size_t)b * NH + h) * NS + s + 8) << 6;
    #pragma unroll
    for (int u = 0; u < 3; u++) {
        float* dst = (u == 0 ? g_Q : u == 1 ? g_K : g_V);
        #pragma unroll
        for (int j = 0; j < 8; j++) {
            *reinterpret_cast<float2*>(dst + base0 + 8*j + 2*t) =
                make_float2(o[u][j][0], o[u][j][1]);
            *reinterpret_cast<float2*>(dst + base1 + 8*j + 2*t) =
                make_float2(o[u][j][2], o[u][j][3]);
        }
    }
}

// ---------------------------------------------------------------------------
// Kernel 2: flash attention, fp16 mma + ldmatrix + register-resident P.
// CTA = (b, h, 128 q rows). 8 warps; warp w owns q rows [16w,16w+16).
// kv tiles of 64, 32 iterations.
// SMEM: Ksh[64][72] K row-major; Vsh[64][72] V row-major (both halves).
//   QK B-frags: ldmatrix.x4 on K rows.  PV B-frags: ldmatrix.x4.trans on V.
//   P = direct register repack of S accumulators (FA2 layout identity).
// ---------------------------------------------------------------------------
#define KSTRh 72
#define VSTRh 72
#define ATTN_SMEM ((64*KSTRh + 64*VSTRh) * 2)

__global__ __launch_bounds__(256, 2) void attn_mma()
{
    extern __shared__ __half hsm[];
    __half* Ksh = hsm;
    __half* Vsh = hsm + 64 * KSTRh;

    int tid  = threadIdx.x;
    int lane = tid & 31;
    int w    = tid >> 5;
    int g    = lane >> 2;
    int t    = lane & 3;

    // ldmatrix per-lane tile addressing offsets
    int rr  = lane & 7;
    int tl  = lane >> 3;           // tile id 0..3
    // QK (non-trans): row = 16p + rr + 8*(tl>>1), col = 16c + 8*(tl&1)
    int k_row_off = rr + 8 * (tl >> 1);
    int k_col_off = 8 * (tl & 1);
    // PV (trans):   row = 16c + rr + 8*(tl&1),  col = 16p + 8*(tl>>1)
    int v_row_off = rr + 8 * (tl & 1);
    int v_col_off = 8 * (tl >> 1);

    uint32_t ks_base = (uint32_t)__cvta_generic_to_shared(Ksh);
    uint32_t vs_base = (uint32_t)__cvta_generic_to_shared(Vsh);

    int bh = blockIdx.x >> 4;
    int qt = blockIdx.x & 15;
    const float* Qg = g_Q + (size_t)bh * NS * NL + (size_t)(qt * 128 + w * 16) * NL;
    const float* Kg = g_K + (size_t)bh * NS * NL;
    const float* Vg = g_V + (size_t)bh * NS * NL;

    const float sc = 0.125f * 1.44269504088896340736f;  // (1/sqrt(64))*log2(e)

    // ---- Q fragments fp16, pre-scaled ----
    uint32_t qa[4][4];
    #pragma unroll
    for (int c = 0; c < 4; c++) {
        const float* r0 = Qg + (size_t)g       * NL + 16*c;
        const float* r1 = Qg + (size_t)(g + 8) * NL + 16*c;
        qa[c][0] = pack_h2(r0[2*t    ] * sc, r0[2*t + 1] * sc);
        qa[c][1] = pack_h2(r1[2*t    ] * sc, r1[2*t + 1] * sc);
        qa[c][2] = pack_h2(r0[2*t + 8] * sc, r0[2*t + 9] * sc);
        qa[c][3] = pack_h2(r1[2*t + 8] * sc, r1[2*t + 9] * sc);
    }

    float o[8][4];
    #pragma unroll
    for (int j = 0; j < 8; j++)
        #pragma unroll
        for (int i = 0; i < 4; i++) o[j][i] = 0.f;
    float m0 = -1e30f, m1 = -1e30f, l0 = 0.f, l1 = 0.f;

    for (int it = 0; it < NS / 64; it++) {
        __syncthreads();
        const float* Kt = Kg + (size_t)it * 64 * NL;
        const float* Vt = Vg + (size_t)it * 64 * NL;
        #pragma unroll
        for (int i = 0; i < 4; i++) {
            int f4 = tid + i * 256;
            int r  = f4 >> 4;
            int c4 = (f4 & 15) << 2;
            float4 kv = *reinterpret_cast<const float4*>(Kt + (size_t)r * NL + c4);
            uint2 kk; kk.x = pack_h2(kv.x, kv.y); kk.y = pack_h2(kv.z, kv.w);
            *reinterpret_cast<uint2*>(&Ksh[r * KSTRh + c4]) = kk;
            float4 vv = *reinterpret_cast<const float4*>(Vt + (size_t)r * NL + c4);
            uint2 vk; vk.x = pack_h2(vv.x, vv.y); vk.y = pack_h2(vv.z, vv.w);
            *reinterpret_cast<uint2*>(&Vsh[r * VSTRh + c4]) = vk;
        }
        __syncthreads();

        // ---- S = Q K^T : n-tile pairs p (kv 16p..+15), k-chunks c ----
        float s[8][4];
        #pragma unroll
        for (int j = 0; j < 8; j++) {
            s[j][0] = s[j][1] = s[j][2] = s[j][3] = 0.f;
        }
        #pragma unroll
        for (int c = 0; c < 4; c++) {
            #pragma unroll
            for (int p = 0; p < 4; p++) {
                uint32_t b0, b1, b2, b3;
                uint32_t addr = ks_base +
                    (uint32_t)(((16*p + k_row_off) * KSTRh + 16*c + k_col_off) * 2);
                ldm_x4(b0, b1, b2, b3, addr);
                mma_f16(s[2*p  ][0], s[2*p  ][1], s[2*p  ][2], s[2*p  ][3],
                        qa[c][0], qa[c][1], qa[c][2], qa[c][3], b0, b1);
                mma_f16(s[2*p+1][0], s[2*p+1][1], s[2*p+1][2], s[2*p+1][3],
                        qa[c][0], qa[c][1], qa[c][2], qa[c][3], b2, b3);
            }
        }

        // ---- online softmax (rows g and g+8; quad reduction) ----
        float mt0 = s[0][0], mt1 = s[0][2];
        #pragma unroll
        for (int j = 0; j < 8; j++) {
            mt0 = fmaxf(mt0, fmaxf(s[j][0], s[j][1]));
            mt1 = fmaxf(mt1, fmaxf(s[j][2], s[j][3]));
        }
        #pragma unroll
        for (int off = 1; off <= 2; off <<= 1) {
            mt0 = fmaxf(mt0, __shfl_xor_sync(0xffffffffu, mt0, off, 4));
            mt1 = fmaxf(mt1, __shfl_xor_sync(0xffffffffu, mt1, off, 4));
        }
        float mn0 = fmaxf(m0, mt0), mn1 = fmaxf(m1, mt1);
        float a0 = fexp2(m0 - mn0), a1 = fexp2(m1 - mn1);
        float ls0 = 0.f, ls1 = 0.f;
        #pragma unroll
        for (int j = 0; j < 8; j++) {
            s[j][0] = fexp2(s[j][0] - mn0); ls0 += s[j][0];
            s[j][1] = fexp2(s[j][1] - mn0); ls0 += s[j][1];
            s[j][2] = fexp2(s[j][2] - mn1); ls1 += s[j][2];
            s[j][3] = fexp2(s[j][3] - mn1); ls1 += s[j][3];
        }
        #pragma unroll
        for (int off = 1; off <= 2; off <<= 1) {
            ls0 += __shfl_xor_sync(0xffffffffu, ls0, off, 4);
            ls1 += __shfl_xor_sync(0xffffffffu, ls1, off, 4);
        }
        l0 = l0 * a0 + ls0; m0 = mn0;
        l1 = l1 * a1 + ls1; m1 = mn1;
        #pragma unroll
        for (int j = 0; j < 8; j++) {
            o[j][0] *= a0; o[j][1] *= a0; o[j][2] *= a1; o[j][3] *= a1;
        }

        // ---- P A-fragments: direct register repack (C layout == A layout) ----
        uint32_t pa[4][4];
        #pragma unroll
        for (int c = 0; c < 4; c++) {
            pa[c][0] = pack_h2(s[2*c  ][0], s[2*c  ][1]);
            pa[c][1] = pack_h2(s[2*c  ][2], s[2*c  ][3]);
            pa[c][2] = pack_h2(s[2*c+1][0], s[2*c+1][1]);
            pa[c][3] = pack_h2(s[2*c+1][2], s[2*c+1][3]);
        }

        // ---- O += P V : out-tile pairs p, kv chunks c (trans ldmatrix) ----
        #pragma unroll
        for (int p = 0; p < 4; p++) {
            #pragma unroll
            for (int c = 0; c < 4; c++) {
                uint32_t b0, b1, b2, b3;
                uint32_t addr = vs_base +
                    (uint32_t)(((16*c + v_row_off) * VSTRh + 16*p + v_col_off) * 2);
                ldm_x4_t(b0, b1, b2, b3, addr);
                mma_f16(o[2*p  ][0], o[2*p  ][1], o[2*p  ][2], o[2*p  ][3],
                        pa[c][0], pa[c][1], pa[c][2], pa[c][3], b0, b1);
                mma_f16(o[2*p+1][0], o[2*p+1][1], o[2*p+1][2], o[2*p+1][3],
                        pa[c][0], pa[c][1], pa[c][2], pa[c][3], b2, b3);
            }
        }
    }

    // ---- normalize + write head-concat layout [b][s][h*64+o] ----
    {
        int b = bh >> 3, h = bh & 7;
        float inv0 = 1.f / l0, inv1 = 1.f / l1;
        int r0 = qt * 128 + w * 16 + g;
        float* p0 = g_O + ((size_t)(b * NS + r0)     * (NH * NL)) + h * NL;
        float* p1 = g_O + ((size_t)(b * NS + r0 + 8) * (NH * NL)) + h * NL;
        #pragma unroll
        for (int j = 0; j < 8; j++) {
            *reinterpret_cast<float2*>(p0 + 8*j + 2*t) =
                make_float2(o[j][0] * inv0, o[j][1] * inv0);
            *reinterpret_cast<float2*>(p1 + 8*j + 2*t) =
                make_float2(o[j][2] * inv1, o[j][3] * inv1);
        }
    }
}

// ---------------------------------------------------------------------------
// Kernel 3: output projection (FFMA; fp32 kept deliberately for accuracy)
// ---------------------------------------------------------------------------
__global__ __launch_bounds__(256) void out_kernel(
    const float* __restrict__ Wo, float* __restrict__ out)
{
    __shared__ float As[16][128];
    __shared__ float Bs[16][64];

    int m0  = blockIdx.x * 128;
    int tid = threadIdx.x;
    int tx  = tid & 15, ty = tid >> 4;

    float acc[8][4];
    #pragma unroll
    for (int i = 0; i < 8; i++)
        #pragma unroll
        for (int j = 0; j < 4; j++) acc[i][j] = 0.f;

    for (int k0 = 0; k0 < ND; k0 += 16) {
        #pragma unroll
        for (int it = 0; it < 2; it++) {
            int f4 = tid + it * 256;
            int r  = f4 >> 2;
            int kc = (f4 & 3) << 2;
            float4 v = *reinterpret_cast<const float4*>(
                g_O + (size_t)(m0 + r) * ND + k0 + kc);
            As[kc+0][r] = v.x; As[kc+1][r] = v.y;
            As[kc+2][r] = v.z; As[kc+3][r] = v.w;
        }
        {
            int r = tid >> 4;
            int c = (tid & 15) << 2;
            *reinterpret_cast<float4*>(&Bs[r][c]) =
                *reinterpret_cast<const float4*>(Wo + (size_t)(k0 + r) * NL + c);
        }
        __syncthreads();

        #pragma unroll
        for (int kk = 0; kk < 16; kk++) {
            float a[8], b[4];
            *reinterpret_cast<float4*>(&a[0]) = *reinterpret_cast<float4*>(&As[kk][ty*8]);
            *reinterpret_cast<float4*>(&a[4]) = *reinterpret_cast<float4*>(&As[kk][ty*8+4]);
            *reinterpret_cast<float4*>(&b[0]) = *reinterpret_cast<float4*>(&Bs[kk][tx*4]);
            #pragma unroll
            for (int i = 0; i < 8; i++)
                #pragma unroll
                for (int j = 0; j < 4; j++)
                    acc[i][j] += a[i] * b[j];
        }
        __syncthreads();
    }

    #pragma unroll
    for (int i = 0; i < 8; i++) {
        int m = m0 + ty * 8 + i;
        float* p = out + (size_t)m * NL + (tx << 2);
        *reinterpret_cast<float4*>(p) =
            make_float4(acc[i][0], acc[i][1], acc[i][2], acc[i][3]);
    }
}

// ---------------------------------------------------------------------------
extern "C" void kernel_launch(void* const* d_in, const int* in_sizes, int n_in,
                              void* d_out, int out_size)
{
    const float* x  = (const float*)d_in[0];
    const float* WQ = (const float*)d_in[1];
    const float* WK = (const float*)d_in[2];
    const float* WV = (const float*)d_in[3];
    const float* WO = (const float*)d_in[4];
    float* out = (float*)d_out;

    cudaFuncSetAttribute(proj_mma, cudaFuncAttributeMaxDynamicSharedMemorySize,
                         PROJ_SMEM);
    proj_mma<<<dim3(128, 8), 256, PROJ_SMEM>>>(x, WQ, WK, WV);

    cudaFuncSetAttribute(attn_mma, cudaFuncAttributeMaxDynamicSharedMemorySize,
                         ATTN_SMEM);
    attn_mma<<<NB * NH * (NS / 128), 256, ATTN_SMEM>>>();

    out_kernel<<<128, 256>>>(WO, out);
}

// round 14
// speedup vs baseline: 5.8709x; 1.0977x over previous
#include <cuda_runtime.h>
#include <cuda_fp16.h>
#include <cstdint>

#define NB 8
#define NS 2048
#define ND 512
#define NH 8
#define NL 64   // LAT == OUT == 64

// Scratch (allocation-free rule: __device__ globals)
__device__ float g_Q[NB*NH*NS*NL];     // [b][h][s][lat]
__device__ float g_K[NB*NH*NS*NL];
__device__ float g_V[NB*NH*NS*NL];
__device__ float g_O[NB*NS*NH*NL];     // [b][s][h*64+o] (head-concat layout)

// ===========================================================================
// helpers
// ===========================================================================
__device__ __forceinline__ float fexp2(float x) {
    float r;
    asm("ex2.approx.ftz.f32 %0, %1;" : "=f"(r) : "f"(x));
    return r;
}
__device__ __forceinline__ uint32_t pack_h2(float a, float b) {
    __half2 h = __floats2half2_rn(a, b);
    return *reinterpret_cast<uint32_t*>(&h);
}
// D += A*B, m16n8k16 fp16 with fp32 accumulate
__device__ __forceinline__ void mma_f16(
    float& d0, float& d1, float& d2, float& d3,
    uint32_t a0, uint32_t a1, uint32_t a2, uint32_t a3,
    uint32_t b0, uint32_t b1)
{
    asm volatile(
        "mma.sync.aligned.m16n8k16.row.col.f32.f16.f16.f32 "
        "{%0,%1,%2,%3}, {%4,%5,%6,%7}, {%8,%9}, {%0,%1,%2,%3};\n"
        : "+f"(d0), "+f"(d1), "+f"(d2), "+f"(d3)
        : "r"(a0), "r"(a1), "r"(a2), "r"(a3), "r"(b0), "r"(b1));
}
__device__ __forceinline__ void ldm_x4(
    uint32_t& r0, uint32_t& r1, uint32_t& r2, uint32_t& r3, uint32_t addr)
{
    asm volatile("ldmatrix.sync.aligned.m8n8.x4.shared.b16 {%0,%1,%2,%3}, [%4];"
                 : "=r"(r0), "=r"(r1), "=r"(r2), "=r"(r3) : "r"(addr));
}
__device__ __forceinline__ void ldm_x4_t(
    uint32_t& r0, uint32_t& r1, uint32_t& r2, uint32_t& r3, uint32_t addr)
{
    asm volatile("ldmatrix.sync.aligned.m8n8.x4.trans.shared.b16 {%0,%1,%2,%3}, [%4];"
                 : "=r"(r0), "=r"(r1), "=r"(r2), "=r"(r3) : "r"(addr));
}

// ---------------------------------------------------------------------------
// Kernel 1: fused QKV projections, fp16 mma + ldmatrix.
// Grid (128 row-tiles, 8 heads). CTA computes Q,K,V [128 x 64] for one head.
// 8 warps, warp w owns rows [16w,16w+16). Accumulators o[3][8][4] (fp32).
//   Xh[128][72] halves row-major          A-frags: ldmatrix.x4
//   Wr[3][64][72] halves row-major [k][n] B-frags: ldmatrix.x4.trans
// (identical fragment scheme to the validated attention kernel)
// ---------------------------------------------------------------------------
#define XSh 72
#define WSh 72
#define PROJ_SMEM ((128*XSh + 3*64*WSh) * 2)

__global__ __launch_bounds__(256, 2) void proj_mma(
    const float* __restrict__ x, const float* __restrict__ WQ,
    const float* __restrict__ WK, const float* __restrict__ WV)
{
    extern __shared__ __half psm[];
    __half* Xh = psm;                 // 128*XSh
    __half* Wr = psm + 128 * XSh;     // 3 * 64*WSh (row-major [k][n])

    int tid  = threadIdx.x;
    int w    = tid >> 5;
    int lane = tid & 31;
    int g    = lane >> 2;
    int t    = lane & 3;

    // ldmatrix lane->tile addressing
    int rr = lane & 7;
    int tl = lane >> 3;
    int a_row_off = rr + 8 * (tl & 1);   // A (non-trans): tiles (0,0),(8,0),(0,8),(8,8)
    int a_col_off = 8 * (tl >> 1);
    int b_row_off = rr + 8 * (tl & 1);   // B (trans): rows = k, cols = n
    int b_col_off = 8 * (tl >> 1);

    uint32_t xs_base = (uint32_t)__cvta_generic_to_shared(Xh);
    uint32_t ws_base = (uint32_t)__cvta_generic_to_shared(Wr);

    int h  = blockIdx.y;
    int m0 = blockIdx.x * 128;
    const float* W0 = WQ + (size_t)h * ND * NL;
    const float* W1 = WK + (size_t)h * ND * NL;
    const float* W2 = WV + (size_t)h * ND * NL;

    float o[3][8][4];
    #pragma unroll
    for (int u = 0; u < 3; u++)
        #pragma unroll
        for (int j = 0; j < 8; j++)
            #pragma unroll
            for (int i = 0; i < 4; i++) o[u][j][i] = 0.f;

    for (int k0 = 0; k0 < ND; k0 += 64) {
        __syncthreads();
        // ---- X tile [128,64] -> halves row-major ----
        #pragma unroll
        for (int i = 0; i < 8; i++) {
            int f4 = tid + i * 256;
            int r  = f4 >> 4;            // 0..127
            int c4 = (f4 & 15) << 2;
            float4 v = *reinterpret_cast<const float4*>(
                x + (size_t)(m0 + r) * ND + k0 + c4);
            uint2 q; q.x = pack_h2(v.x, v.y); q.y = pack_h2(v.z, v.w);
            *reinterpret_cast<uint2*>(&Xh[r * XSh + c4]) = q;
        }
        // ---- W tiles [64k,64n] x3 -> halves row-major (no transpose!) ----
        #pragma unroll
        for (int u = 0; u < 3; u++) {
            const float* Wg = (u == 0 ? W0 : u == 1 ? W1 : W2);
            __half* Wu = Wr + u * 64 * WSh;
            #pragma unroll
            for (int i = 0; i < 4; i++) {
                int f4 = tid + i * 256;
                int r  = f4 >> 4;        // 0..63 (k row)
                int c4 = (f4 & 15) << 2;
                float4 v = *reinterpret_cast<const float4*>(
                    Wg + (size_t)(k0 + r) * NL + c4);
                uint2 q; q.x = pack_h2(v.x, v.y); q.y = pack_h2(v.z, v.w);
                *reinterpret_cast<uint2*>(&Wu[r * WSh + c4]) = q;
            }
        }
        __syncthreads();

        // ---- MMA: 4 k-chunks of 16; outputs u; n-tile pairs p ----
        #pragma unroll
        for (int c = 0; c < 4; c++) {
            uint32_t a0, a1, a2, a3;
            uint32_t aaddr = xs_base +
                (uint32_t)(((16*w + a_row_off) * XSh + 16*c + a_col_off) * 2);
            ldm_x4(a0, a1, a2, a3, aaddr);
            #pragma unroll
            for (int u = 0; u < 3; u++) {
                uint32_t wu_base = ws_base + (uint32_t)(u * 64 * WSh * 2);
                #pragma unroll
                for (int p = 0; p < 4; p++) {
                    uint32_t b0, b1, b2, b3;
                    uint32_t baddr = wu_base +
                        (uint32_t)(((16*c + b_row_off) * WSh + 16*p + b_col_off) * 2);
                    ldm_x4_t(b0, b1, b2, b3, baddr);
                    mma_f16(o[u][2*p  ][0], o[u][2*p  ][1], o[u][2*p  ][2], o[u][2*p  ][3],
                            a0, a1, a2, a3, b0, b1);
                    mma_f16(o[u][2*p+1][0], o[u][2*p+1][1], o[u][2*p+1][2], o[u][2*p+1][3],
                            a0, a1, a2, a3, b2, b3);
                }
            }
        }
    }

    // write to [b][h][s][64]
    int m = m0 + 16 * w + g;
    int b = m >> 11, s = m & 2047;
    size_t base0 = (((size_t)b * NH + h) * NS + s)     << 6;
    size_t base1 = (((size_t)b * NH + h) * NS + s + 8) << 6;
    #pragma unroll
    for (int u = 0; u < 3; u++) {
        float* dst = (u == 0 ? g_Q : u == 1 ? g_K : g_V);
        #pragma unroll
        for (int j = 0; j < 8; j++) {
            *reinterpret_cast<float2*>(dst + base0 + 8*j + 2*t) =
                make_float2(o[u][j][0], o[u][j][1]);
            *reinterpret_cast<float2*>(dst + base1 + 8*j + 2*t) =
                make_float2(o[u][j][2], o[u][j][3]);
        }
    }
}

// ---------------------------------------------------------------------------
// Kernel 2: flash attention, fp16 mma + ldmatrix + register-resident P.
// (unchanged from R11)
// ---------------------------------------------------------------------------
#define KSTRh 72
#define VSTRh 72
#define ATTN_SMEM ((64*KSTRh + 64*VSTRh) * 2)

__global__ __launch_bounds__(256, 2) void attn_mma()
{
    extern __shared__ __half hsm[];
    __half* Ksh = hsm;
    __half* Vsh = hsm + 64 * KSTRh;

    int tid  = threadIdx.x;
    int lane = tid & 31;
    int w    = tid >> 5;
    int g    = lane >> 2;
    int t    = lane & 3;

    int rr  = lane & 7;
    int tl  = lane >> 3;
    int k_row_off = rr + 8 * (tl >> 1);
    int k_col_off = 8 * (tl & 1);
    int v_row_off = rr + 8 * (tl & 1);
    int v_col_off = 8 * (tl >> 1);

    uint32_t ks_base = (uint32_t)__cvta_generic_to_shared(Ksh);
    uint32_t vs_base = (uint32_t)__cvta_generic_to_shared(Vsh);

    int bh = blockIdx.x >> 4;
    int qt = blockIdx.x & 15;
    const float* Qg = g_Q + (size_t)bh * NS * NL + (size_t)(qt * 128 + w * 16) * NL;
    const float* Kg = g_K + (size_t)bh * NS * NL;
    const float* Vg = g_V + (size_t)bh * NS * NL;

    const float sc = 0.125f * 1.44269504088896340736f;

    uint32_t qa[4][4];
    #pragma unroll
    for (int c = 0; c < 4; c++) {
        const float* r0 = Qg + (size_t)g       * NL + 16*c;
        const float* r1 = Qg + (size_t)(g + 8) * NL + 16*c;
        qa[c][0] = pack_h2(r0[2*t    ] * sc, r0[2*t + 1] * sc);
        qa[c][1] = pack_h2(r1[2*t    ] * sc, r1[2*t + 1] * sc);
        qa[c][2] = pack_h2(r0[2*t + 8] * sc, r0[2*t + 9] * sc);
        qa[c][3] = pack_h2(r1[2*t + 8] * sc, r1[2*t + 9] * sc);
    }

    float o[8][4];
    #pragma unroll
    for (int j = 0; j < 8; j++)
        #pragma unroll
        for (int i = 0; i < 4; i++) o[j][i] = 0.f;
    float m0 = -1e30f, m1 = -1e30f, l0 = 0.f, l1 = 0.f;

    for (int it = 0; it < NS / 64; it++) {
        __syncthreads();
        const float* Kt = Kg + (size_t)it * 64 * NL;
        const float* Vt = Vg + (size_t)it * 64 * NL;
        #pragma unroll
        for (int i = 0; i < 4; i++) {
            int f4 = tid + i * 256;
            int r  = f4 >> 4;
            int c4 = (f4 & 15) << 2;
            float4 kv = *reinterpret_cast<const float4*>(Kt + (size_t)r * NL + c4);
            uint2 kk; kk.x = pack_h2(kv.x, kv.y); kk.y = pack_h2(kv.z, kv.w);
            *reinterpret_cast<uint2*>(&Ksh[r * KSTRh + c4]) = kk;
            float4 vv = *reinterpret_cast<const float4*>(Vt + (size_t)r * NL + c4);
            uint2 vk; vk.x = pack_h2(vv.x, vv.y); vk.y = pack_h2(vv.z, vv.w);
            *reinterpret_cast<uint2*>(&Vsh[r * VSTRh + c4]) = vk;
        }
        __syncthreads();

        float s[8][4];
        #pragma unroll
        for (int j = 0; j < 8; j++) {
            s[j][0] = s[j][1] = s[j][2] = s[j][3] = 0.f;
        }
        #pragma unroll
        for (int c = 0; c < 4; c++) {
            #pragma unroll
            for (int p = 0; p < 4; p++) {
                uint32_t b0, b1, b2, b3;
                uint32_t addr = ks_base +
                    (uint32_t)(((16*p + k_row_off) * KSTRh + 16*c + k_col_off) * 2);
                ldm_x4(b0, b1, b2, b3, addr);
                mma_f16(s[2*p  ][0], s[2*p  ][1], s[2*p  ][2], s[2*p  ][3],
                        qa[c][0], qa[c][1], qa[c][2], qa[c][3], b0, b1);
                mma_f16(s[2*p+1][0], s[2*p+1][1], s[2*p+1][2], s[2*p+1][3],
                        qa[c][0], qa[c][1], qa[c][2], qa[c][3], b2, b3);
            }
        }

        float mt0 = s[0][0], mt1 = s[0][2];
        #pragma unroll
        for (int j = 0; j < 8; j++) {
            mt0 = fmaxf(mt0, fmaxf(s[j][0], s[j][1]));
            mt1 = fmaxf(mt1, fmaxf(s[j][2], s[j][3]));
        }
        #pragma unroll
        for (int off = 1; off <= 2; off <<= 1) {
            mt0 = fmaxf(mt0, __shfl_xor_sync(0xffffffffu, mt0, off, 4));
            mt1 = fmaxf(mt1, __shfl_xor_sync(0xffffffffu, mt1, off, 4));
        }
        float mn0 = fmaxf(m0, mt0), mn1 = fmaxf(m1, mt1);
        float a0 = fexp2(m0 - mn0), a1 = fexp2(m1 - mn1);
        float ls0 = 0.f, ls1 = 0.f;
        #pragma unroll
        for (int j = 0; j < 8; j++) {
            s[j][0] = fexp2(s[j][0] - mn0); ls0 += s[j][0];
            s[j][1] = fexp2(s[j][1] - mn0); ls0 += s[j][1];
            s[j][2] = fexp2(s[j][2] - mn1); ls1 += s[j][2];
            s[j][3] = fexp2(s[j][3] - mn1); ls1 += s[j][3];
        }
        #pragma unroll
        for (int off = 1; off <= 2; off <<= 1) {
            ls0 += __shfl_xor_sync(0xffffffffu, ls0, off, 4);
            ls1 += __shfl_xor_sync(0xffffffffu, ls1, off, 4);
        }
        l0 = l0 * a0 + ls0; m0 = mn0;
        l1 = l1 * a1 + ls1; m1 = mn1;
        #pragma unroll
        for (int j = 0; j < 8; j++) {
            o[j][0] *= a0; o[j][1] *= a0; o[j][2] *= a1; o[j][3] *= a1;
        }

        uint32_t pa[4][4];
        #pragma unroll
        for (int c = 0; c < 4; c++) {
            pa[c][0] = pack_h2(s[2*c  ][0], s[2*c  ][1]);
            pa[c][1] = pack_h2(s[2*c  ][2], s[2*c  ][3]);
            pa[c][2] = pack_h2(s[2*c+1][0], s[2*c+1][1]);
            pa[c][3] = pack_h2(s[2*c+1][2], s[2*c+1][3]);
        }

        #pragma unroll
        for (int p = 0; p < 4; p++) {
            #pragma unroll
            for (int c = 0; c < 4; c++) {
                uint32_t b0, b1, b2, b3;
                uint32_t addr = vs_base +
                    (uint32_t)(((16*c + v_row_off) * VSTRh + 16*p + v_col_off) * 2);
                ldm_x4_t(b0, b1, b2, b3, addr);
                mma_f16(o[2*p  ][0], o[2*p  ][1], o[2*p  ][2], o[2*p  ][3],
                        pa[c][0], pa[c][1], pa[c][2], pa[c][3], b0, b1);
                mma_f16(o[2*p+1][0], o[2*p+1][1], o[2*p+1][2], o[2*p+1][3],
                        pa[c][0], pa[c][1], pa[c][2], pa[c][3], b2, b3);
            }
        }
    }

    {
        int b = bh >> 3, h = bh & 7;
        float inv0 = 1.f / l0, inv1 = 1.f / l1;
        int r0 = qt * 128 + w * 16 + g;
        float* p0 = g_O + ((size_t)(b * NS + r0)     * (NH * NL)) + h * NL;
        float* p1 = g_O + ((size_t)(b * NS + r0 + 8) * (NH * NL)) + h * NL;
        #pragma unroll
        for (int j = 0; j < 8; j++) {
            *reinterpret_cast<float2*>(p0 + 8*j + 2*t) =
                make_float2(o[j][0] * inv0, o[j][1] * inv0);
            *reinterpret_cast<float2*>(p1 + 8*j + 2*t) =
                make_float2(o[j][2] * inv1, o[j][3] * inv1);
        }
    }
}

// ---------------------------------------------------------------------------
// Kernel 3: output projection (FFMA; fp32 kept deliberately for accuracy)
// ---------------------------------------------------------------------------
__global__ __launch_bounds__(256) void out_kernel(
    const float* __restrict__ Wo, float* __restrict__ out)
{
    __shared__ float As[16][128];
    __shared__ float Bs[16][64];

    int m0  = blockIdx.x * 128;
    int tid = threadIdx.x;
    int tx  = tid & 15, ty = tid >> 4;

    float acc[8][4];
    #pragma unroll
    for (int i = 0; i < 8; i++)
        #pragma unroll
        for (int j = 0; j < 4; j++) acc[i][j] = 0.f;

    for (int k0 = 0; k0 < ND; k0 += 16) {
        #pragma unroll
        for (int it = 0; it < 2; it++) {
            int f4 = tid + it * 256;
            int r  = f4 >> 2;
            int kc = (f4 & 3) << 2;
            float4 v = *reinterpret_cast<const float4*>(
                g_O + (size_t)(m0 + r) * ND + k0 + kc);
            As[kc+0][r] = v.x; As[kc+1][r] = v.y;
            As[kc+2][r] = v.z; As[kc+3][r] = v.w;
        }
        {
            int r = tid >> 4;
            int c = (tid & 15) << 2;
            *reinterpret_cast<float4*>(&Bs[r][c]) =
                *reinterpret_cast<const float4*>(Wo + (size_t)(k0 + r) * NL + c);
        }
        __syncthreads();

        #pragma unroll
        for (int kk = 0; kk < 16; kk++) {
            float a[8], b[4];
            *reinterpret_cast<float4*>(&a[0]) = *reinterpret_cast<float4*>(&As[kk][ty*8]);
            *reinterpret_cast<float4*>(&a[4]) = *reinterpret_cast<float4*>(&As[kk][ty*8+4]);
            *reinterpret_cast<float4*>(&b[0]) = *reinterpret_cast<float4*>(&Bs[kk][tx*4]);
            #pragma unroll
            for (int i = 0; i < 8; i++)
                #pragma unroll
                for (int j = 0; j < 4; j++)
                    acc[i][j] += a[i] * b[j];
        }
        __syncthreads();
    }

    #pragma unroll
    for (int i = 0; i < 8; i++) {
        int m = m0 + ty * 8 + i;
        float* p = out + (size_t)m * NL + (tx << 2);
        *reinterpret_cast<float4*>(p) =
            make_float4(acc[i][0], acc[i][1], acc[i][2], acc[i][3]);
    }
}

// ---------------------------------------------------------------------------
extern "C" void kernel_launch(void* const* d_in, const int* in_sizes, int n_in,
                              void* d_out, int out_size)
{
    const float* x  = (const float*)d_in[0];
    const float* WQ = (const float*)d_in[1];
    const float* WK = (const float*)d_in[2];
    const float* WV = (const float*)d_in[3];
    const float* WO = (const float*)d_in[4];
    float* out = (float*)d_out;

    cudaFuncSetAttribute(proj_mma, cudaFuncAttributeMaxDynamicSharedMemorySize,
                         PROJ_SMEM);
    proj_mma<<<dim3(128, 8), 256, PROJ_SMEM>>>(x, WQ, WK, WV);

    cudaFuncSetAttribute(attn_mma, cudaFuncAttributeMaxDynamicSharedMemorySize,
                         ATTN_SMEM);
    attn_mma<<<NB * NH * (NS / 128), 256, ATTN_SMEM>>>();

    out_kernel<<<128, 256>>>(WO, out);
}

// round 15
// speedup vs baseline: 6.6033x; 1.1247x over previous
#include <cuda_runtime.h>
#include <cuda_fp16.h>
#include <cstdint>

#define NB 8
#define NS 2048
#define ND 512
#define NH 8
#define NL 64   // LAT == OUT == 64

// Scratch (allocation-free rule: __device__ globals)
__device__ __half g_Qh[NB*NH*NS*NL];   // [b][h][s][lat], pre-scaled by sc
__device__ __half g_Kh[NB*NH*NS*NL];
__device__ __half g_Vh[NB*NH*NS*NL];
__device__ float  g_O [NB*NS*NH*NL];   // [b][s][h*64+o] (head-concat layout)

// ===========================================================================
// helpers
// ===========================================================================
__device__ __forceinline__ float fexp2(float x) {
    float r;
    asm("ex2.approx.ftz.f32 %0, %1;" : "=f"(r) : "f"(x));
    return r;
}
__device__ __forceinline__ uint32_t pack_h2(float a, float b) {
    __half2 h = __floats2half2_rn(a, b);
    return *reinterpret_cast<uint32_t*>(&h);
}
// D += A*B, m16n8k16 fp16 with fp32 accumulate
__device__ __forceinline__ void mma_f16(
    float& d0, float& d1, float& d2, float& d3,
    uint32_t a0, uint32_t a1, uint32_t a2, uint32_t a3,
    uint32_t b0, uint32_t b1)
{
    asm volatile(
        "mma.sync.aligned.m16n8k16.row.col.f32.f16.f16.f32 "
        "{%0,%1,%2,%3}, {%4,%5,%6,%7}, {%8,%9}, {%0,%1,%2,%3};\n"
        : "+f"(d0), "+f"(d1), "+f"(d2), "+f"(d3)
        : "r"(a0), "r"(a1), "r"(a2), "r"(a3), "r"(b0), "r"(b1));
}
__device__ __forceinline__ void ldm_x4(
    uint32_t& r0, uint32_t& r1, uint32_t& r2, uint32_t& r3, uint32_t addr)
{
    asm volatile("ldmatrix.sync.aligned.m8n8.x4.shared.b16 {%0,%1,%2,%3}, [%4];"
                 : "=r"(r0), "=r"(r1), "=r"(r2), "=r"(r3) : "r"(addr));
}
__device__ __forceinline__ void ldm_x4_t(
    uint32_t& r0, uint32_t& r1, uint32_t& r2, uint32_t& r3, uint32_t addr)
{
    asm volatile("ldmatrix.sync.aligned.m8n8.x4.trans.shared.b16 {%0,%1,%2,%3}, [%4];"
                 : "=r"(r0), "=r"(r1), "=r"(r2), "=r"(r3) : "r"(addr));
}
__device__ __forceinline__ void cp16(uint32_t dst, const void* src) {
    asm volatile("cp.async.cg.shared.global [%0], [%1], 16;"
                 :: "r"(dst), "l"(src) : "memory");
}

// ---------------------------------------------------------------------------
// Kernel 1: fused QKV projections, fp16 mma + ldmatrix. Outputs fp16.
// ---------------------------------------------------------------------------
#define XSh 72
#define WSh 72
#define PROJ_SMEM ((128*XSh + 3*64*WSh) * 2)

__global__ __launch_bounds__(256, 2) void proj_mma(
    const float* __restrict__ x, const float* __restrict__ WQ,
    const float* __restrict__ WK, const float* __restrict__ WV)
{
    extern __shared__ __half psm[];
    __half* Xh = psm;                 // 128*XSh
    __half* Wr = psm + 128 * XSh;     // 3 * 64*WSh (row-major [k][n])

    int tid  = threadIdx.x;
    int w    = tid >> 5;
    int lane = tid & 31;
    int g    = lane >> 2;
    int t    = lane & 3;

    int rr = lane & 7;
    int tl = lane >> 3;
    int a_row_off = rr + 8 * (tl & 1);
    int a_col_off = 8 * (tl >> 1);
    int b_row_off = rr + 8 * (tl & 1);
    int b_col_off = 8 * (tl >> 1);

    uint32_t xs_base = (uint32_t)__cvta_generic_to_shared(Xh);
    uint32_t ws_base = (uint32_t)__cvta_generic_to_shared(Wr);

    int h  = blockIdx.y;
    int m0 = blockIdx.x * 128;
    const float* W0 = WQ + (size_t)h * ND * NL;
    const float* W1 = WK + (size_t)h * ND * NL;
    const float* W2 = WV + (size_t)h * ND * NL;

    float o[3][8][4];
    #pragma unroll
    for (int u = 0; u < 3; u++)
        #pragma unroll
        for (int j = 0; j < 8; j++)
            #pragma unroll
            for (int i = 0; i < 4; i++) o[u][j][i] = 0.f;

    for (int k0 = 0; k0 < ND; k0 += 64) {
        __syncthreads();
        #pragma unroll
        for (int i = 0; i < 8; i++) {
            int f4 = tid + i * 256;
            int r  = f4 >> 4;
            int c4 = (f4 & 15) << 2;
            float4 v = *reinterpret_cast<const float4*>(
                x + (size_t)(m0 + r) * ND + k0 + c4);
            uint2 q; q.x = pack_h2(v.x, v.y); q.y = pack_h2(v.z, v.w);
            *reinterpret_cast<uint2*>(&Xh[r * XSh + c4]) = q;
        }
        #pragma unroll
        for (int u = 0; u < 3; u++) {
            const float* Wg = (u == 0 ? W0 : u == 1 ? W1 : W2);
            __half* Wu = Wr + u * 64 * WSh;
            #pragma unroll
            for (int i = 0; i < 4; i++) {
                int f4 = tid + i * 256;
                int r  = f4 >> 4;
                int c4 = (f4 & 15) << 2;
                float4 v = *reinterpret_cast<const float4*>(
                    Wg + (size_t)(k0 + r) * NL + c4);
                uint2 q; q.x = pack_h2(v.x, v.y); q.y = pack_h2(v.z, v.w);
                *reinterpret_cast<uint2*>(&Wu[r * WSh + c4]) = q;
            }
        }
        __syncthreads();

        #pragma unroll
        for (int c = 0; c < 4; c++) {
            uint32_t a0, a1, a2, a3;
            uint32_t aaddr = xs_base +
                (uint32_t)(((16*w + a_row_off) * XSh + 16*c + a_col_off) * 2);
            ldm_x4(a0, a1, a2, a3, aaddr);
            #pragma unroll
            for (int u = 0; u < 3; u++) {
                uint32_t wu_base = ws_base + (uint32_t)(u * 64 * WSh * 2);
                #pragma unroll
                for (int p = 0; p < 4; p++) {
                    uint32_t b0, b1, b2, b3;
                    uint32_t baddr = wu_base +
                        (uint32_t)(((16*c + b_row_off) * WSh + 16*p + b_col_off) * 2);
                    ldm_x4_t(b0, b1, b2, b3, baddr);
                    mma_f16(o[u][2*p  ][0], o[u][2*p  ][1], o[u][2*p  ][2], o[u][2*p  ][3],
                            a0, a1, a2, a3, b0, b1);
                    mma_f16(o[u][2*p+1][0], o[u][2*p+1][1], o[u][2*p+1][2], o[u][2*p+1][3],
                            a0, a1, a2, a3, b2, b3);
                }
            }
        }
    }

    // write fp16 to [b][h][s][64]; Q pre-scaled by sc
    const float sc = 0.125f * 1.44269504088896340736f;
    int m = m0 + 16 * w + g;
    int b = m >> 11, s = m & 2047;
    size_t base0 = (((size_t)b * NH + h) * NS + s)     << 6;
    size_t base1 = (((size_t)b * NH + h) * NS + s + 8) << 6;
    #pragma unroll
    for (int j = 0; j < 8; j++) {
        *reinterpret_cast<uint32_t*>(g_Qh + base0 + 8*j + 2*t) =
            pack_h2(o[0][j][0]*sc, o[0][j][1]*sc);
        *reinterpret_cast<uint32_t*>(g_Qh + base1 + 8*j + 2*t) =
            pack_h2(o[0][j][2]*sc, o[0][j][3]*sc);
        *reinterpret_cast<uint32_t*>(g_Kh + base0 + 8*j + 2*t) =
            pack_h2(o[1][j][0], o[1][j][1]);
        *reinterpret_cast<uint32_t*>(g_Kh + base1 + 8*j + 2*t) =
            pack_h2(o[1][j][2], o[1][j][3]);
        *reinterpret_cast<uint32_t*>(g_Vh + base0 + 8*j + 2*t) =
            pack_h2(o[2][j][0], o[2][j][1]);
        *reinterpret_cast<uint32_t*>(g_Vh + base1 + 8*j + 2*t) =
            pack_h2(o[2][j][2], o[2][j][3]);
    }
}

// ---------------------------------------------------------------------------
// Kernel 2: flash attention, fp16 mma + ldmatrix + register P +
// cp.async double-buffered K/V staging (fp16 gmem, no conversion).
// SMEM: Ksh[2][64*72], Vsh[2][64*72] halves.
// ---------------------------------------------------------------------------
#define KSTRh 72
#define TILE_H (64 * KSTRh)            // halves per buffer
#define TILE_B (TILE_H * 2)            // bytes per buffer
#define ATTN_SMEM (4 * TILE_B)

__global__ __launch_bounds__(256, 2) void attn_mma()
{
    extern __shared__ __half hsm[];
    uint32_t sm_base = (uint32_t)__cvta_generic_to_shared(hsm);
    uint32_t ks_base = sm_base;                 // buffers 0,1
    uint32_t vs_base = sm_base + 2 * TILE_B;    // buffers 0,1

    int tid  = threadIdx.x;
    int lane = tid & 31;
    int w    = tid >> 5;
    int g    = lane >> 2;
    int t    = lane & 3;

    int rr  = lane & 7;
    int tl  = lane >> 3;
    int k_row_off = rr + 8 * (tl >> 1);
    int k_col_off = 8 * (tl & 1);
    int v_row_off = rr + 8 * (tl & 1);
    int v_col_off = 8 * (tl >> 1);

    int bh = blockIdx.x >> 4;
    int qt = blockIdx.x & 15;
    const __half* Qg = g_Qh + (size_t)bh * NS * NL + (size_t)(qt * 128 + w * 16) * NL;
    const __half* Kg = g_Kh + (size_t)bh * NS * NL;
    const __half* Vg = g_Vh + (size_t)bh * NS * NL;

    // staging coords: 2 chunks of 16B per tensor per thread
    int st_r0 = tid >> 3,           st_c0 = (tid & 7) * 8;
    int st_r1 = (tid + 256) >> 3,   st_c1 = (tid & 7) * 8;

    // ---- Q fragments: direct u32 loads (pre-scaled fp16) ----
    uint32_t qa[4][4];
    #pragma unroll
    for (int c = 0; c < 4; c++) {
        const __half* r0 = Qg + (size_t)g       * NL + 16*c;
        const __half* r1 = Qg + (size_t)(g + 8) * NL + 16*c;
        qa[c][0] = *reinterpret_cast<const uint32_t*>(r0 + 2*t    );
        qa[c][1] = *reinterpret_cast<const uint32_t*>(r1 + 2*t    );
        qa[c][2] = *reinterpret_cast<const uint32_t*>(r0 + 2*t + 8);
        qa[c][3] = *reinterpret_cast<const uint32_t*>(r1 + 2*t + 8);
    }

    float o[8][4];
    #pragma unroll
    for (int j = 0; j < 8; j++)
        #pragma unroll
        for (int i = 0; i < 4; i++) o[j][i] = 0.f;
    float m0 = -1e30f, m1 = -1e30f, l0 = 0.f, l1 = 0.f;

    // ---- prologue: stage tile 0 into buffer 0 ----
    {
        const __half* Kt = Kg;
        const __half* Vt = Vg;
        cp16(ks_base + (uint32_t)((st_r0 * KSTRh + st_c0) * 2), Kt + st_r0 * NL + st_c0);
        cp16(ks_base + (uint32_t)((st_r1 * KSTRh + st_c1) * 2), Kt + st_r1 * NL + st_c1);
        cp16(vs_base + (uint32_t)((st_r0 * KSTRh + st_c0) * 2), Vt + st_r0 * NL + st_c0);
        cp16(vs_base + (uint32_t)((st_r1 * KSTRh + st_c1) * 2), Vt + st_r1 * NL + st_c1);
        asm volatile("cp.async.commit_group;" ::: "memory");
    }

    for (int it = 0; it < NS / 64; it++) {
        int cur = it & 1;
        if (it + 1 < NS / 64) {
            // stage next tile into other buffer
            uint32_t koff = ks_base + (uint32_t)((cur ^ 1) * TILE_B);
            uint32_t voff = vs_base + (uint32_t)((cur ^ 1) * TILE_B);
            const __half* Kt = Kg + (size_t)(it + 1) * 64 * NL;
            const __half* Vt = Vg + (size_t)(it + 1) * 64 * NL;
            cp16(koff + (uint32_t)((st_r0 * KSTRh + st_c0) * 2), Kt + st_r0 * NL + st_c0);
            cp16(koff + (uint32_t)((st_r1 * KSTRh + st_c1) * 2), Kt + st_r1 * NL + st_c1);
            cp16(voff + (uint32_t)((st_r0 * KSTRh + st_c0) * 2), Vt + st_r0 * NL + st_c0);
            cp16(voff + (uint32_t)((st_r1 * KSTRh + st_c1) * 2), Vt + st_r1 * NL + st_c1);
            asm volatile("cp.async.commit_group;" ::: "memory");
            asm volatile("cp.async.wait_group 1;" ::: "memory");
        } else {
            asm volatile("cp.async.wait_group 0;" ::: "memory");
        }
        __syncthreads();

        uint32_t kb = ks_base + (uint32_t)(cur * TILE_B);
        uint32_t vb = vs_base + (uint32_t)(cur * TILE_B);

        // ---- S = Q K^T ----
        float s[8][4];
        #pragma unroll
        for (int j = 0; j < 8; j++) {
            s[j][0] = s[j][1] = s[j][2] = s[j][3] = 0.f;
        }
        #pragma unroll
        for (int c = 0; c < 4; c++) {
            #pragma unroll
            for (int p = 0; p < 4; p++) {
                uint32_t b0, b1, b2, b3;
                uint32_t addr = kb +
                    (uint32_t)(((16*p + k_row_off) * KSTRh + 16*c + k_col_off) * 2);
                ldm_x4(b0, b1, b2, b3, addr);
                mma_f16(s[2*p  ][0], s[2*p  ][1], s[2*p  ][2], s[2*p  ][3],
                        qa[c][0], qa[c][1], qa[c][2], qa[c][3], b0, b1);
                mma_f16(s[2*p+1][0], s[2*p+1][1], s[2*p+1][2], s[2*p+1][3],
                        qa[c][0], qa[c][1], qa[c][2], qa[c][3], b2, b3);
            }
        }

        // ---- online softmax ----
        float mt0 = s[0][0], mt1 = s[0][2];
        #pragma unroll
        for (int j = 0; j < 8; j++) {
            mt0 = fmaxf(mt0, fmaxf(s[j][0], s[j][1]));
            mt1 = fmaxf(mt1, fmaxf(s[j][2], s[j][3]));
        }
        #pragma unroll
        for (int off = 1; off <= 2; off <<= 1) {
            mt0 = fmaxf(mt0, __shfl_xor_sync(0xffffffffu, mt0, off, 4));
            mt1 = fmaxf(mt1, __shfl_xor_sync(0xffffffffu, mt1, off, 4));
        }
        float mn0 = fmaxf(m0, mt0), mn1 = fmaxf(m1, mt1);
        float a0 = fexp2(m0 - mn0), a1 = fexp2(m1 - mn1);
        float ls0 = 0.f, ls1 = 0.f;
        #pragma unroll
        for (int j = 0; j < 8; j++) {
            s[j][0] = fexp2(s[j][0] - mn0); ls0 += s[j][0];
            s[j][1] = fexp2(s[j][1] - mn0); ls0 += s[j][1];
            s[j][2] = fexp2(s[j][2] - mn1); ls1 += s[j][2];
            s[j][3] = fexp2(s[j][3] - mn1); ls1 += s[j][3];
        }
        #pragma unroll
        for (int off = 1; off <= 2; off <<= 1) {
            ls0 += __shfl_xor_sync(0xffffffffu, ls0, off, 4);
            ls1 += __shfl_xor_sync(0xffffffffu, ls1, off, 4);
        }
        l0 = l0 * a0 + ls0; m0 = mn0;
        l1 = l1 * a1 + ls1; m1 = mn1;
        #pragma unroll
        for (int j = 0; j < 8; j++) {
            o[j][0] *= a0; o[j][1] *= a0; o[j][2] *= a1; o[j][3] *= a1;
        }

        // ---- P A-fragments (register repack) ----
        uint32_t pa[4][4];
        #pragma unroll
        for (int c = 0; c < 4; c++) {
            pa[c][0] = pack_h2(s[2*c  ][0], s[2*c  ][1]);
            pa[c][1] = pack_h2(s[2*c  ][2], s[2*c  ][3]);
            pa[c][2] = pack_h2(s[2*c+1][0], s[2*c+1][1]);
            pa[c][3] = pack_h2(s[2*c+1][2], s[2*c+1][3]);
        }

        // ---- O += P V ----
        #pragma unroll
        for (int p = 0; p < 4; p++) {
            #pragma unroll
            for (int c = 0; c < 4; c++) {
                uint32_t b0, b1, b2, b3;
                uint32_t addr = vb +
                    (uint32_t)(((16*c + v_row_off) * KSTRh + 16*p + v_col_off) * 2);
                ldm_x4_t(b0, b1, b2, b3, addr);
                mma_f16(o[2*p  ][0], o[2*p  ][1], o[2*p  ][2], o[2*p  ][3],
                        pa[c][0], pa[c][1], pa[c][2], pa[c][3], b0, b1);
                mma_f16(o[2*p+1][0], o[2*p+1][1], o[2*p+1][2], o[2*p+1][3],
                        pa[c][0], pa[c][1], pa[c][2], pa[c][3], b2, b3);
            }
        }
        __syncthreads();   // protect buffer cur before it is overwritten
    }

    // ---- normalize + write head-concat layout [b][s][h*64+o] ----
    {
        int b = bh >> 3, h = bh & 7;
        float inv0 = 1.f / l0, inv1 = 1.f / l1;
        int r0 = qt * 128 + w * 16 + g;
        float* p0 = g_O + ((size_t)(b * NS + r0)     * (NH * NL)) + h * NL;
        float* p1 = g_O + ((size_t)(b * NS + r0 + 8) * (NH * NL)) + h * NL;
        #pragma unroll
        for (int j = 0; j < 8; j++) {
            *reinterpret_cast<float2*>(p0 + 8*j + 2*t) =
                make_float2(o[j][0] * inv0, o[j][1] * inv0);
            *reinterpret_cast<float2*>(p1 + 8*j + 2*t) =
                make_float2(o[j][2] * inv1, o[j][3] * inv1);
        }
    }
}

// ---------------------------------------------------------------------------
// Kernel 3: output projection (FFMA; fp32 kept deliberately for accuracy)
// ---------------------------------------------------------------------------
__global__ __launch_bounds__(256) void out_kernel(
    const float* __restrict__ Wo, float* __restrict__ out)
{
    __shared__ float As[16][128];
    __shared__ float Bs[16][64];

    int m0  = blockIdx.x * 128;
    int tid = threadIdx.x;
    int tx  = tid & 15, ty = tid >> 4;

    float acc[8][4];
    #pragma unroll
    for (int i = 0; i < 8; i++)
        #pragma unroll
        for (int j = 0; j < 4; j++) acc[i][j] = 0.f;

    for (int k0 = 0; k0 < ND; k0 += 16) {
        #pragma unroll
        for (int it = 0; it < 2; it++) {
            int f4 = tid + it * 256;
            int r  = f4 >> 2;
            int kc = (f4 & 3) << 2;
            float4 v = *reinterpret_cast<const float4*>(
                g_O + (size_t)(m0 + r) * ND + k0 + kc);
            As[kc+0][r] = v.x; As[kc+1][r] = v.y;
            As[kc+2][r] = v.z; As[kc+3][r] = v.w;
        }
        {
            int r = tid >> 4;
            int c = (tid & 15) << 2;
            *reinterpret_cast<float4*>(&Bs[r][c]) =
                *reinterpret_cast<const float4*>(Wo + (size_t)(k0 + r) * NL + c);
        }
        __syncthreads();

        #pragma unroll
        for (int kk = 0; kk < 16; kk++) {
            float a[8], b[4];
            *reinterpret_cast<float4*>(&a[0]) = *reinterpret_cast<float4*>(&As[kk][ty*8]);
            *reinterpret_cast<float4*>(&a[4]) = *reinterpret_cast<float4*>(&As[kk][ty*8+4]);
            *reinterpret_cast<float4*>(&b[0]) = *reinterpret_cast<float4*>(&Bs[kk][tx*4]);
            #pragma unroll
            for (int i = 0; i < 8; i++)
                #pragma unroll
                for (int j = 0; j < 4; j++)
                    acc[i][j] += a[i] * b[j];
        }
        __syncthreads();
    }

    #pragma unroll
    for (int i = 0; i < 8; i++) {
        int m = m0 + ty * 8 + i;
        float* p = out + (size_t)m * NL + (tx << 2);
        *reinterpret_cast<float4*>(p) =
            make_float4(acc[i][0], acc[i][1], acc[i][2], acc[i][3]);
    }
}

// ---------------------------------------------------------------------------
extern "C" void kernel_launch(void* const* d_in, const int* in_sizes, int n_in,
                              void* d_out, int out_size)
{
    const float* x  = (const float*)d_in[0];
    const float* WQ = (const float*)d_in[1];
    const float* WK = (const float*)d_in[2];
    const float* WV = (const float*)d_in[3];
    const float* WO = (const float*)d_in[4];
    float* out = (float*)d_out;

    cudaFuncSetAttribute(proj_mma, cudaFuncAttributeMaxDynamicSharedMemorySize,
                         PROJ_SMEM);
    proj_mma<<<dim3(128, 8), 256, PROJ_SMEM>>>(x, WQ, WK, WV);

    cudaFuncSetAttribute(attn_mma, cudaFuncAttributeMaxDynamicSharedMemorySize,
                         ATTN_SMEM);
    attn_mma<<<NB * NH * (NS / 128), 256, ATTN_SMEM>>>();

    out_kernel<<<128, 256>>>(WO, out);
}

// round 17
// speedup vs baseline: 7.5107x; 1.1374x over previous
#include <cuda_runtime.h>
#include <cuda_fp16.h>
#include <cstdint>

#define NB 8
#define NS 2048
#define ND 512
#define NH 8
#define NL 64   // LAT == OUT == 64

// Scratch (allocation-free rule: __device__ globals)
__device__ __half g_Xh[NB*NS*ND];      // x in fp16, [b*s][d]
__device__ __half g_Wh[3*NH*ND*NL];    // WQ|WK|WV fp16, [u][h][d][n]
__device__ __half g_Qh[NB*NH*NS*NL];   // [b][h][s][lat], pre-scaled by sc
__device__ __half g_Kh[NB*NH*NS*NL];
__device__ __half g_Vh[NB*NH*NS*NL];
__device__ float  g_O [NB*NS*NH*NL];   // [b][s][h*64+o] (head-concat layout)

// ===========================================================================
// helpers
// ===========================================================================
__device__ __forceinline__ float fexp2(float x) {
    float r;
    asm("ex2.approx.ftz.f32 %0, %1;" : "=f"(r) : "f"(x));
    return r;
}
__device__ __forceinline__ uint32_t pack_h2(float a, float b) {
    __half2 h = __floats2half2_rn(a, b);
    return *reinterpret_cast<uint32_t*>(&h);
}
__device__ __forceinline__ void mma_f16(
    float& d0, float& d1, float& d2, float& d3,
    uint32_t a0, uint32_t a1, uint32_t a2, uint32_t a3,
    uint32_t b0, uint32_t b1)
{
    asm volatile(
        "mma.sync.aligned.m16n8k16.row.col.f32.f16.f16.f32 "
        "{%0,%1,%2,%3}, {%4,%5,%6,%7}, {%8,%9}, {%0,%1,%2,%3};\n"
        : "+f"(d0), "+f"(d1), "+f"(d2), "+f"(d3)
        : "r"(a0), "r"(a1), "r"(a2), "r"(a3), "r"(b0), "r"(b1));
}
__device__ __forceinline__ void ldm_x4(
    uint32_t& r0, uint32_t& r1, uint32_t& r2, uint32_t& r3, uint32_t addr)
{
    asm volatile("ldmatrix.sync.aligned.m8n8.x4.shared.b16 {%0,%1,%2,%3}, [%4];"
                 : "=r"(r0), "=r"(r1), "=r"(r2), "=r"(r3) : "r"(addr));
}
__device__ __forceinline__ void ldm_x4_t(
    uint32_t& r0, uint32_t& r1, uint32_t& r2, uint32_t& r3, uint32_t addr)
{
    asm volatile("ldmatrix.sync.aligned.m8n8.x4.trans.shared.b16 {%0,%1,%2,%3}, [%4];"
                 : "=r"(r0), "=r"(r1), "=r"(r2), "=r"(r3) : "r"(addr));
}
__device__ __forceinline__ void cp16(uint32_t dst, const void* src) {
    asm volatile("cp.async.cg.shared.global [%0], [%1], 16;"
                 :: "r"(dst), "l"(src) : "memory");
}

// ---------------------------------------------------------------------------
// Kernel 0: fp32 -> fp16 conversion of x and the QKV weights.
// ---------------------------------------------------------------------------
__global__ __launch_bounds__(256) void cvt_kernel(
    const float* __restrict__ x, const float* __restrict__ WQ,
    const float* __restrict__ WK, const float* __restrict__ WV)
{
    const int NX4 = NB*NS*ND/4;        // float4 count for x
    const int NW4 = NH*ND*NL/4;        // per weight tensor
    int total = NX4 + 3*NW4;
    for (int i = blockIdx.x * blockDim.x + threadIdx.x; i < total;
         i += gridDim.x * blockDim.x) {
        const float* src; __half* dst; int k;
        if (i < NX4)                 { src = x;  dst = g_Xh;              k = i; }
        else if (i < NX4 + NW4)      { src = WQ; dst = g_Wh;              k = i - NX4; }
        else if (i < NX4 + 2*NW4)    { src = WK; dst = g_Wh + NH*ND*NL;   k = i - NX4 - NW4; }
        else                         { src = WV; dst = g_Wh + 2*NH*ND*NL; k = i - NX4 - 2*NW4; }
        float4 v = reinterpret_cast<const float4*>(src)[k];
        uint2 q; q.x = pack_h2(v.x, v.y); q.y = pack_h2(v.z, v.w);
        reinterpret_cast<uint2*>(dst)[k] = q;
    }
}

// ---------------------------------------------------------------------------
// Kernel 1: fused QKV projections, fp16 mma + ldmatrix + cp.async pipeline.
// Grid (128 row-tiles, 8 heads). 8 warps. Double-buffered X and W tiles.
// SMEM per buffer: Xb[128][72] + Wb[3][64][72] halves = 46080 B; x2 = 90 KB.
// ---------------------------------------------------------------------------
#define PSTRp 72
#define XT_H (128 * PSTRp)                 // halves
#define WT_H (64 * PSTRp)                  // per-u halves
#define PBUF_B ((XT_H + 3 * WT_H) * 2)     // bytes per buffer
#define PROJ_SMEM (2 * PBUF_B)

__global__ __launch_bounds__(256, 2) void proj_mma()
{
    extern __shared__ __half psm[];
    uint32_t base = (uint32_t)__cvta_generic_to_shared(psm);

    int tid  = threadIdx.x;
    int w    = tid >> 5;
    int lane = tid & 31;
    int g    = lane >> 2;
    int t    = lane & 3;

    int rr = lane & 7;
    int tl = lane >> 3;
    int a_row_off = rr + 8 * (tl & 1);
    int a_col_off = 8 * (tl >> 1);
    int b_row_off = rr + 8 * (tl & 1);
    int b_col_off = 8 * (tl >> 1);

    int h  = blockIdx.y;
    int m0 = blockIdx.x * 128;
    const __half* Xg = g_Xh + (size_t)m0 * ND;
    const __half* Wg[3];
    Wg[0] = g_Wh + ((size_t)0*NH + h) * ND * NL;
    Wg[1] = g_Wh + ((size_t)1*NH + h) * ND * NL;
    Wg[2] = g_Wh + ((size_t)2*NH + h) * ND * NL;

    // staging coords (16B = 8 halves chunks)
    int xr0 = tid >> 1,  xc0 = (tid & 1) * 8;       // X: k-cols 0..15 of 64? no:
    // X tile is 128 rows x 64 halves = 8 chunks/row, 1024 chunks, 4/thread
    // W tile (per u) 64 rows x 64 halves = 512 chunks, 2/thread

    auto stage = [&](int buf, int k0) {
        uint32_t xb = base + (uint32_t)(buf * PBUF_B);
        #pragma unroll
        for (int i = 0; i < 4; i++) {
            int id = tid + i * 256;
            int r = id >> 3, c = (id & 7) * 8;
            cp16(xb + (uint32_t)((r * PSTRp + c) * 2),
                 Xg + (size_t)r * ND + k0 + c);
        }
        #pragma unroll
        for (int u = 0; u < 3; u++) {
            uint32_t wb = xb + (uint32_t)((XT_H + u * WT_H) * 2);
            #pragma unroll
            for (int i = 0; i < 2; i++) {
                int id = tid + i * 256;
                int r = id >> 3, c = (id & 7) * 8;
                cp16(wb + (uint32_t)((r * PSTRp + c) * 2),
                     Wg[u] + (size_t)(k0 + r) * NL + c);
            }
        }
        asm volatile("cp.async.commit_group;" ::: "memory");
    };

    float o[3][8][4];
    #pragma unroll
    for (int u = 0; u < 3; u++)
        #pragma unroll
        for (int j = 0; j < 8; j++)
            #pragma unroll
            for (int i = 0; i < 4; i++) o[u][j][i] = 0.f;

    stage(0, 0);

    for (int kt = 0; kt < ND / 64; kt++) {
        int cur = kt & 1;
        if (kt + 1 < ND / 64) {
            stage(cur ^ 1, (kt + 1) * 64);
            asm volatile("cp.async.wait_group 1;" ::: "memory");
        } else {
            asm volatile("cp.async.wait_group 0;" ::: "memory");
        }
        __syncthreads();

        uint32_t xb = base + (uint32_t)(cur * PBUF_B);

        #pragma unroll
        for (int c = 0; c < 4; c++) {
            uint32_t a0, a1, a2, a3;
            uint32_t aaddr = xb +
                (uint32_t)(((16*w + a_row_off) * PSTRp + 16*c + a_col_off) * 2);
            ldm_x4(a0, a1, a2, a3, aaddr);
            #pragma unroll
            for (int u = 0; u < 3; u++) {
                uint32_t wb = xb + (uint32_t)((XT_H + u * WT_H) * 2);
                #pragma unroll
                for (int p = 0; p < 4; p++) {
                    uint32_t b0, b1, b2, b3;
                    uint32_t baddr = wb +
                        (uint32_t)(((16*c + b_row_off) * PSTRp + 16*p + b_col_off) * 2);
                    ldm_x4_t(b0, b1, b2, b3, baddr);
                    mma_f16(o[u][2*p  ][0], o[u][2*p  ][1], o[u][2*p  ][2], o[u][2*p  ][3],
                            a0, a1, a2, a3, b0, b1);
                    mma_f16(o[u][2*p+1][0], o[u][2*p+1][1], o[u][2*p+1][2], o[u][2*p+1][3],
                            a0, a1, a2, a3, b2, b3);
                }
            }
        }
        __syncthreads();
    }

    // write fp16 to [b][h][s][64]; Q pre-scaled by sc
    const float sc = 0.125f * 1.44269504088896340736f;
    int m = m0 + 16 * w + g;
    int b = m >> 11, s = m & 2047;
    size_t base0 = (((size_t)b * NH + h) * NS + s)     << 6;
    size_t base1 = (((size_t)b * NH + h) * NS + s + 8) << 6;
    #pragma unroll
    for (int j = 0; j < 8; j++) {
        *reinterpret_cast<uint32_t*>(g_Qh + base0 + 8*j + 2*t) =
            pack_h2(o[0][j][0]*sc, o[0][j][1]*sc);
        *reinterpret_cast<uint32_t*>(g_Qh + base1 + 8*j + 2*t) =
            pack_h2(o[0][j][2]*sc, o[0][j][3]*sc);
        *reinterpret_cast<uint32_t*>(g_Kh + base0 + 8*j + 2*t) =
            pack_h2(o[1][j][0], o[1][j][1]);
        *reinterpret_cast<uint32_t*>(g_Kh + base1 + 8*j + 2*t) =
            pack_h2(o[1][j][2], o[1][j][3]);
        *reinterpret_cast<uint32_t*>(g_Vh + base0 + 8*j + 2*t) =
            pack_h2(o[2][j][0], o[2][j][1]);
        *reinterpret_cast<uint32_t*>(g_Vh + base1 + 8*j + 2*t) =
            pack_h2(o[2][j][2], o[2][j][3]);
    }
}

// ---------------------------------------------------------------------------
// Kernel 2: flash attention. (unchanged from R15)
// ---------------------------------------------------------------------------
#define KSTRh 72
#define TILE_H (64 * KSTRh)
#define TILE_B (TILE_H * 2)
#define ATTN_SMEM (4 * TILE_B)

__global__ __launch_bounds__(256, 2) void attn_mma()
{
    extern __shared__ __half hsm[];
    uint32_t sm_base = (uint32_t)__cvta_generic_to_shared(hsm);
    uint32_t ks_base = sm_base;
    uint32_t vs_base = sm_base + 2 * TILE_B;

    int tid  = threadIdx.x;
    int lane = tid & 31;
    int w    = tid >> 5;
    int g    = lane >> 2;
    int t    = lane & 3;

    int rr  = lane & 7;
    int tl  = lane >> 3;
    int k_row_off = rr + 8 * (tl >> 1);
    int k_col_off = 8 * (tl & 1);
    int v_row_off = rr + 8 * (tl & 1);
    int v_col_off = 8 * (tl >> 1);

    int bh = blockIdx.x >> 4;
    int qt = blockIdx.x & 15;
    const __half* Qg = g_Qh + (size_t)bh * NS * NL + (size_t)(qt * 128 + w * 16) * NL;
    const __half* Kg = g_Kh + (size_t)bh * NS * NL;
    const __half* Vg = g_Vh + (size_t)bh * NS * NL;

    int st_r0 = tid >> 3,           st_c0 = (tid & 7) * 8;
    int st_r1 = (tid + 256) >> 3,   st_c1 = (tid & 7) * 8;

    uint32_t qa[4][4];
    #pragma unroll
    for (int c = 0; c < 4; c++) {
        const __half* r0 = Qg + (size_t)g       * NL + 16*c;
        const __half* r1 = Qg + (size_t)(g + 8) * NL + 16*c;
        qa[c][0] = *reinterpret_cast<const uint32_t*>(r0 + 2*t    );
        qa[c][1] = *reinterpret_cast<const uint32_t*>(r1 + 2*t    );
        qa[c][2] = *reinterpret_cast<const uint32_t*>(r0 + 2*t + 8);
        qa[c][3] = *reinterpret_cast<const uint32_t*>(r1 + 2*t + 8);
    }

    float o[8][4];
    #pragma unroll
    for (int j = 0; j < 8; j++)
        #pragma unroll
        for (int i = 0; i < 4; i++) o[j][i] = 0.f;
    float m0 = -1e30f, m1 = -1e30f, l0 = 0.f, l1 = 0.f;

    {
        cp16(ks_base + (uint32_t)((st_r0 * KSTRh + st_c0) * 2), Kg + st_r0 * NL + st_c0);
        cp16(ks_base + (uint32_t)((st_r1 * KSTRh + st_c1) * 2), Kg + st_r1 * NL + st_c1);
        cp16(vs_base + (uint32_t)((st_r0 * KSTRh + st_c0) * 2), Vg + st_r0 * NL + st_c0);
        cp16(vs_base + (uint32_t)((st_r1 * KSTRh + st_c1) * 2), Vg + st_r1 * NL + st_c1);
        asm volatile("cp.async.commit_group;" ::: "memory");
    }

    for (int it = 0; it < NS / 64; it++) {
        int cur = it & 1;
        if (it + 1 < NS / 64) {
            uint32_t koff = ks_base + (uint32_t)((cur ^ 1) * TILE_B);
            uint32_t voff = vs_base + (uint32_t)((cur ^ 1) * TILE_B);
            const __half* Kt = Kg + (size_t)(it + 1) * 64 * NL;
            const __half* Vt = Vg + (size_t)(it + 1) * 64 * NL;
            cp16(koff + (uint32_t)((st_r0 * KSTRh + st_c0) * 2), Kt + st_r0 * NL + st_c0);
            cp16(koff + (uint32_t)((st_r1 * KSTRh + st_c1) * 2), Kt + st_r1 * NL + st_c1);
            cp16(voff + (uint32_t)((st_r0 * KSTRh + st_c0) * 2), Vt + st_r0 * NL + st_c0);
            cp16(voff + (uint32_t)((st_r1 * KSTRh + st_c1) * 2), Vt + st_r1 * NL + st_c1);
            asm volatile("cp.async.commit_group;" ::: "memory");
            asm volatile("cp.async.wait_group 1;" ::: "memory");
        } else {
            asm volatile("cp.async.wait_group 0;" ::: "memory");
        }
        __syncthreads();

        uint32_t kb = ks_base + (uint32_t)(cur * TILE_B);
        uint32_t vb = vs_base + (uint32_t)(cur * TILE_B);

        float s[8][4];
        #pragma unroll
        for (int j = 0; j < 8; j++) {
            s[j][0] = s[j][1] = s[j][2] = s[j][3] = 0.f;
        }
        #pragma unroll
        for (int c = 0; c < 4; c++) {
            #pragma unroll
            for (int p = 0; p < 4; p++) {
                uint32_t b0, b1, b2, b3;
                uint32_t addr = kb +
                    (uint32_t)(((16*p + k_row_off) * KSTRh + 16*c + k_col_off) * 2);
                ldm_x4(b0, b1, b2, b3, addr);
                mma_f16(s[2*p  ][0], s[2*p  ][1], s[2*p  ][2], s[2*p  ][3],
                        qa[c][0], qa[c][1], qa[c][2], qa[c][3], b0, b1);
                mma_f16(s[2*p+1][0], s[2*p+1][1], s[2*p+1][2], s[2*p+1][3],
                        qa[c][0], qa[c][1], qa[c][2], qa[c][3], b2, b3);
            }
        }

        float mt0 = s[0][0], mt1 = s[0][2];
        #pragma unroll
        for (int j = 0; j < 8; j++) {
            mt0 = fmaxf(mt0, fmaxf(s[j][0], s[j][1]));
            mt1 = fmaxf(mt1, fmaxf(s[j][2], s[j][3]));
        }
        #pragma unroll
        for (int off = 1; off <= 2; off <<= 1) {
            mt0 = fmaxf(mt0, __shfl_xor_sync(0xffffffffu, mt0, off, 4));
            mt1 = fmaxf(mt1, __shfl_xor_sync(0xffffffffu, mt1, off, 4));
        }
        float mn0 = fmaxf(m0, mt0), mn1 = fmaxf(m1, mt1);
        float a0 = fexp2(m0 - mn0), a1 = fexp2(m1 - mn1);
        float ls0 = 0.f, ls1 = 0.f;
        #pragma unroll
        for (int j = 0; j < 8; j++) {
            s[j][0] = fexp2(s[j][0] - mn0); ls0 += s[j][0];
            s[j][1] = fexp2(s[j][1] - mn0); ls0 += s[j][1];
            s[j][2] = fexp2(s[j][2] - mn1); ls1 += s[j][2];
            s[j][3] = fexp2(s[j][3] - mn1); ls1 += s[j][3];
        }
        #pragma unroll
        for (int off = 1; off <= 2; off <<= 1) {
            ls0 += __shfl_xor_sync(0xffffffffu, ls0, off, 4);
            ls1 += __shfl_xor_sync(0xffffffffu, ls1, off, 4);
        }
        l0 = l0 * a0 + ls0; m0 = mn0;
        l1 = l1 * a1 + ls1; m1 = mn1;
        #pragma unroll
        for (int j = 0; j < 8; j++) {
            o[j][0] *= a0; o[j][1] *= a0; o[j][2] *= a1; o[j][3] *= a1;
        }

        uint32_t pa[4][4];
        #pragma unroll
        for (int c = 0; c < 4; c++) {
            pa[c][0] = pack_h2(s[2*c  ][0], s[2*c  ][1]);
            pa[c][1] = pack_h2(s[2*c  ][2], s[2*c  ][3]);
            pa[c][2] = pack_h2(s[2*c+1][0], s[2*c+1][1]);
            pa[c][3] = pack_h2(s[2*c+1][2], s[2*c+1][3]);
        }

        #pragma unroll
        for (int p = 0; p < 4; p++) {
            #pragma unroll
            for (int c = 0; c < 4; c++) {
                uint32_t b0, b1, b2, b3;
                uint32_t addr = vb +
                    (uint32_t)(((16*c + v_row_off) * KSTRh + 16*p + v_col_off) * 2);
                ldm_x4_t(b0, b1, b2, b3, addr);
                mma_f16(o[2*p  ][0], o[2*p  ][1], o[2*p  ][2], o[2*p  ][3],
                        pa[c][0], pa[c][1], pa[c][2], pa[c][3], b0, b1);
                mma_f16(o[2*p+1][0], o[2*p+1][1], o[2*p+1][2], o[2*p+1][3],
                        pa[c][0], pa[c][1], pa[c][2], pa[c][3], b2, b3);
            }
        }
        __syncthreads();
    }

    {
        int b = bh >> 3, h = bh & 7;
        float inv0 = 1.f / l0, inv1 = 1.f / l1;
        int r0 = qt * 128 + w * 16 + g;
        float* p0 = g_O + ((size_t)(b * NS + r0)     * (NH * NL)) + h * NL;
        float* p1 = g_O + ((size_t)(b * NS + r0 + 8) * (NH * NL)) + h * NL;
        #pragma unroll
        for (int j = 0; j < 8; j++) {
            *reinterpret_cast<float2*>(p0 + 8*j + 2*t) =
                make_float2(o[j][0] * inv0, o[j][1] * inv0);
            *reinterpret_cast<float2*>(p1 + 8*j + 2*t) =
                make_float2(o[j][2] * inv1, o[j][3] * inv1);
        }
    }
}

// ---------------------------------------------------------------------------
// Kernel 3: output projection (FFMA; fp32 kept deliberately for accuracy)
// ---------------------------------------------------------------------------
__global__ __launch_bounds__(256) void out_kernel(
    const float* __restrict__ Wo, float* __restrict__ out)
{
    __shared__ float As[16][128];
    __shared__ float Bs[16][64];

    int m0  = blockIdx.x * 128;
    int tid = threadIdx.x;
    int tx  = tid & 15, ty = tid >> 4;

    float acc[8][4];
    #pragma unroll
    for (int i = 0; i < 8; i++)
        #pragma unroll
        for (int j = 0; j < 4; j++) acc[i][j] = 0.f;

    for (int k0 = 0; k0 < ND; k0 += 16) {
        #pragma unroll
        for (int it = 0; it < 2; it++) {
            int f4 = tid + it * 256;
            int r  = f4 >> 2;
            int kc = (f4 & 3) << 2;
            float4 v = *reinterpret_cast<const float4*>(
                g_O + (size_t)(m0 + r) * ND + k0 + kc);
            As[kc+0][r] = v.x; As[kc+1][r] = v.y;
            As[kc+2][r] = v.z; As[kc+3][r] = v.w;
        }
        {
            int r = tid >> 4;
            int c = (tid & 15) << 2;
            *reinterpret_cast<float4*>(&Bs[r][c]) =
                *reinterpret_cast<const float4*>(Wo + (size_t)(k0 + r) * NL + c);
        }
        __syncthreads();

        #pragma unroll
        for (int kk = 0; kk < 16; kk++) {
            float a[8], b[4];
            *reinterpret_cast<float4*>(&a[0]) = *reinterpret_cast<float4*>(&As[kk][ty*8]);
            *reinterpret_cast<float4*>(&a[4]) = *reinterpret_cast<float4*>(&As[kk][ty*8+4]);
            *reinterpret_cast<float4*>(&b[0]) = *reinterpret_cast<float4*>(&Bs[kk][tx*4]);
            #pragma unroll
            for (int i = 0; i < 8; i++)
                #pragma unroll
                for (int j = 0; j < 4; j++)
                    acc[i][j] += a[i] * b[j];
        }
        __syncthreads();
    }

    #pragma unroll
    for (int i = 0; i < 8; i++) {
        int m = m0 + ty * 8 + i;
        float* p = out + (size_t)m * NL + (tx << 2);
        *reinterpret_cast<float4*>(p) =
            make_float4(acc[i][0], acc[i][1], acc[i][2], acc[i][3]);
    }
}

// ---------------------------------------------------------------------------
extern "C" void kernel_launch(void* const* d_in, const int* in_sizes, int n_in,
                              void* d_out, int out_size)
{
    const float* x  = (const float*)d_in[0];
    const float* WQ = (const float*)d_in[1];
    const float* WK = (const float*)d_in[2];
    const float* WV = (const float*)d_in[3];
    const float* WO = (const float*)d_in[4];
    float* out = (float*)d_out;

    cvt_kernel<<<1184, 256>>>(x, WQ, WK, WV);

    cudaFuncSetAttribute(proj_mma, cudaFuncAttributeMaxDynamicSharedMemorySize,
                         PROJ_SMEM);
    proj_mma<<<dim3(128, 8), 256, PROJ_SMEM>>>();

    cudaFuncSetAttribute(attn_mma, cudaFuncAttributeMaxDynamicSharedMemorySize,
                         ATTN_SMEM);
    attn_mma<<<NB * NH * (NS / 128), 256, ATTN_SMEM>>>();

    out_kernel<<<128, 256>>>(WO, out);
}